// round 14
// baseline (speedup 1.0000x reference)
#include <cuda_runtime.h>
#include <math.h>
#include <stdint.h>

// Problem constants
constexpr int Bn = 8, Sn = 1024, Dn = 512, Hn = 8, HD = 64, Fn = 2048;
constexpr int Mtok = Bn * Sn; // 8192
constexpr int D3 = 3 * Dn;    // 1536
constexpr int NROWS = Bn * Hn * Sn;   // 65536 attention rows

// Scratch (static device globals; no runtime allocation)
__device__ float  gQKV [(size_t)Mtok * D3];          // packed Q|K|V rows
__device__ float  gWcat[Dn * D3];
__device__ float  gBcat[D3];
__device__ float  gS   [(size_t)Bn * Hn * Sn * Sn];  // 256 MB raw scores
__device__ float2 gOvf [(size_t)NROWS * Sn];         // overflow spill (rarely touched)
__device__ float  gCtx [Mtok * Dn];
__device__ float  gY   [Mtok * Dn];
__device__ float  gX1  [Mtok * Dn];
__device__ float  gH1  [(size_t)Mtok * Fn];
__device__ float  gY2  [Mtok * Dn];

enum { EPI_NONE = 0, EPI_BIAS = 1, EPI_MISH = 2 };

// mish(x) = x*tanh(softplus(x)); with t=e^x, tanh(ln(1+t)) = (t^2+2t)/(t^2+2t+2)
__device__ __forceinline__ float mish_f(float v) {
    if (v > 20.f) return v;
    float t = __expf(v);
    float u = fmaf(t, t, 2.f * t);
    return __fdividef(v * u, u + 2.f);
}

__device__ __forceinline__ float to_tf32(float x) {
    float r;
    asm("cvt.rna.tf32.f32 %0, %1;" : "=f"(r) : "f"(x));
    return r;
}

__device__ __forceinline__ void cpa16(float* smem_dst, const float* gsrc) {
    uint32_t a = (uint32_t)__cvta_generic_to_shared(smem_dst);
    asm volatile("cp.async.cg.shared.global [%0], [%1], 16;" :: "r"(a), "l"(gsrc));
}
__device__ __forceinline__ void cp_commit() {
    asm volatile("cp.async.commit_group;");
}
template <int NN>
__device__ __forceinline__ void cp_wait() {
    asm volatile("cp.async.wait_group %0;" :: "n"(NN));
}

__device__ __forceinline__ void mma_tf32(float* acc, const uint32_t* a, const uint32_t* b) {
    asm volatile(
        "mma.sync.aligned.m16n8k8.row.col.f32.tf32.tf32.f32 "
        "{%0,%1,%2,%3}, {%4,%5,%6,%7}, {%8,%9}, {%0,%1,%2,%3};"
        : "+f"(acc[0]), "+f"(acc[1]), "+f"(acc[2]), "+f"(acc[3])
        : "r"(a[0]), "r"(a[1]), "r"(a[2]), "r"(a[3]), "r"(b[0]), "r"(b[1]));
}

// Host/device-consistent smem sizing (3-stage pipeline)
constexpr size_t tg_smem_bytes(int BM, int BN, int BK, bool BT) {
    int as = BM * (BK + 4);
    int bs = BT ? BN * (BK + 4) : BK * (BN + 8);
    return (size_t)(as + bs) * 3 * sizeof(float);
}

// ---------------------------------------------------------------------------
// tf32 tensor-core GEMM, 3-stage cp.async pipeline: C = A @ B (+bias)(+mish).
// BTRANS: B stored [N,K] (K contiguous) -> C = A @ B^T.
// ---------------------------------------------------------------------------
template <int BM, int BN, int BK, int WM, int WN, int EPI, bool BTRANS>
__global__ __launch_bounds__(256, 2)
void tgemm(const float* __restrict__ Ag, const float* __restrict__ Bg,
           const float* __restrict__ bias, float* __restrict__ Cg,
           int M, int N, int K, int lda, int ldb, int ldc,
           long long sA_b, long long sA_h,
           long long sB_b, long long sB_h,
           long long sC_b, long long sC_h, int Hdiv)
{
    constexpr int WARPS_N = BN / WN;
    constexpr int MI = WM / 16;
    constexpr int NI = WN / 8;
    constexpr int ASTR = BK + 4;
    constexpr int BNP  = BN + 8;
    constexpr int KQ   = BK / 4;             // 16B chunks per row
    constexpr int BS_ELEMS = BTRANS ? BN * ASTR : BK * BNP;

    extern __shared__ __align__(16) float dsm[];
    float* AsBase = dsm;                          // 3 * BM * ASTR
    float* BsBase = dsm + 3 * BM * ASTR;          // 3 * BS_ELEMS

    int z  = blockIdx.z;
    int bb = z / Hdiv, hh = z - bb * Hdiv;
    const float* A = Ag + (size_t)bb * sA_b + (size_t)hh * sA_h;
    const float* B = Bg + (size_t)bb * sB_b + (size_t)hh * sB_h;
    float*       C = Cg + (size_t)bb * sC_b + (size_t)hh * sC_h;

    const int tid  = threadIdx.x;
    const int lane = tid & 31;
    const int w    = tid >> 5;
    const int gid  = lane >> 2;   // 0..7
    const int tig  = lane & 3;    // 0..3
    const int wm0  = (w / WARPS_N) * WM;
    const int wn0  = (w % WARPS_N) * WN;
    const int m0   = blockIdx.y * BM;
    const int n0   = blockIdx.x * BN;

    float acc[MI][NI][4];
#pragma unroll
    for (int i = 0; i < MI; i++)
#pragma unroll
        for (int j = 0; j < NI; j++)
#pragma unroll
            for (int c = 0; c < 4; c++) acc[i][j][c] = 0.f;

    const int nTiles = K / BK;

    auto load_tile = [&](int kt, int buf) {
        float* As = AsBase + buf * (BM * ASTR);
        float* Bs = BsBase + buf * BS_ELEMS;
#pragma unroll
        for (int i = tid; i < BM * KQ; i += 256) {
            int m = i / KQ, kc = (i % KQ) * 4;
            cpa16(&As[m * ASTR + kc], A + (size_t)(m0 + m) * lda + kt * BK + kc);
        }
        if (BTRANS) {
#pragma unroll
            for (int i = tid; i < BN * KQ; i += 256) {
                int n = i / KQ, kc = (i % KQ) * 4;
                cpa16(&Bs[n * ASTR + kc], B + (size_t)(n0 + n) * ldb + kt * BK + kc);
            }
        } else {
#pragma unroll
            for (int i = tid; i < BK * BN / 4; i += 256) {
                int kr = i / (BN / 4), nq = (i % (BN / 4)) * 4;
                cpa16(&Bs[kr * BNP + nq], B + (size_t)(kt * BK + kr) * ldb + n0 + nq);
            }
        }
        cp_commit();
    };

    load_tile(0, 0);
    load_tile(1, 1);

    for (int kt = 0; kt < nTiles; kt++) {
        if (kt + 1 >= nTiles) cp_wait<0>(); else cp_wait<1>();
        __syncthreads();
        if (kt + 2 < nTiles) load_tile(kt + 2, (kt + 2) % 3);

        int buf = kt % 3;
        const float* As = AsBase + buf * (BM * ASTR);
        const float* Bs = BsBase + buf * BS_ELEMS;

#pragma unroll
        for (int ks = 0; ks < BK; ks += 8) {
            uint32_t af[MI][4], bf[NI][2];
#pragma unroll
            for (int mi = 0; mi < MI; mi++) {
                const float* ap = As + (wm0 + mi * 16 + gid) * ASTR + ks + tig;
                af[mi][0] = __float_as_uint(to_tf32(ap[0]));
                af[mi][1] = __float_as_uint(to_tf32(ap[8 * ASTR]));
                af[mi][2] = __float_as_uint(to_tf32(ap[4]));
                af[mi][3] = __float_as_uint(to_tf32(ap[8 * ASTR + 4]));
            }
#pragma unroll
            for (int ni = 0; ni < NI; ni++) {
                if (BTRANS) {
                    const float* bp = Bs + (wn0 + ni * 8 + gid) * ASTR + ks + tig;
                    bf[ni][0] = __float_as_uint(to_tf32(bp[0]));
                    bf[ni][1] = __float_as_uint(to_tf32(bp[4]));
                } else {
                    const float* bp = Bs + (ks + tig) * BNP + wn0 + ni * 8 + gid;
                    bf[ni][0] = __float_as_uint(to_tf32(bp[0]));
                    bf[ni][1] = __float_as_uint(to_tf32(bp[4 * BNP]));
                }
            }
#pragma unroll
            for (int mi = 0; mi < MI; mi++)
#pragma unroll
                for (int ni = 0; ni < NI; ni++)
                    mma_tf32(acc[mi][ni], af[mi], bf[ni]);
        }
    }

    // --- Epilogue ---
#pragma unroll
    for (int mi = 0; mi < MI; mi++) {
#pragma unroll
        for (int ni = 0; ni < NI; ni++) {
            int row = m0 + wm0 + mi * 16 + gid;
            int col = n0 + wn0 + ni * 8 + tig * 2;
            float b0 = 0.f, b1 = 0.f;
            if (EPI >= 1) { b0 = bias[col]; b1 = bias[col + 1]; }
            float v0 = acc[mi][ni][0] + b0, v1 = acc[mi][ni][1] + b1;
            float v2 = acc[mi][ni][2] + b0, v3 = acc[mi][ni][3] + b1;
            if (EPI == 2) { v0 = mish_f(v0); v1 = mish_f(v1); v2 = mish_f(v2); v3 = mish_f(v3); }
            *(float2*)(C + (size_t)row * ldc + col)       = make_float2(v0, v1);
            *(float2*)(C + (size_t)(row + 8) * ldc + col) = make_float2(v2, v3);
        }
    }
}

// ---------------------------------------------------------------------------
// Pack Wq|Wk|Wv -> gWcat [512][1536], biases -> gBcat [1536]
// ---------------------------------------------------------------------------
__global__ __launch_bounds__(256)
void concat_qkv(const float* __restrict__ Wq, const float* __restrict__ Wk,
                const float* __restrict__ Wv,
                const float* __restrict__ bq, const float* __restrict__ bk,
                const float* __restrict__ bv,
                float* __restrict__ Wcat, float* __restrict__ bcat)
{
    int i = blockIdx.x * 256 + threadIdx.x;
    if (i < Dn * Dn) {
        int k = i >> 9, n = i & 511;
        Wcat[k * D3 + n]          = Wq[i];
        Wcat[k * D3 + Dn + n]     = Wk[i];
        Wcat[k * D3 + 2 * Dn + n] = Wv[i];
    }
    if (i < Dn) {
        bcat[i]          = bq[i];
        bcat[Dn + i]     = bk[i];
        bcat[2 * Dn + i] = bv[i];
    }
}

// ---------------------------------------------------------------------------
// Fused entmax-1.5 + sparse attn@V, TWO warps per attention row
// (16 score elements per thread -> ~50 regs -> higher occupancy).
// Cross-warp-pair reductions via smem + __syncthreads (all solver passes
// have fixed trip counts, so barriers are uniform across the block).
// Phase A: raw-domain tau solve (max, 3 bisect, 2 Newton, final sums +
//          closed form via SY = s1 + c*t, SY2 = s2 + 2t*s1 + c*t^2).
// Phase B: compact support {y > T} into smem (cap 128; global spill).
// Phase C: both warps gather interleaved halves of sum p_j * V[idx_j,:],
//          combine per-lane partials through smem.
// ---------------------------------------------------------------------------
constexpr int SUP_CAP = 128;

__global__ __launch_bounds__(256)
void entmax_pv(const float* __restrict__ S, const float* __restrict__ qkv,
               float2* __restrict__ Ovf, float* __restrict__ ctx)
{
    __shared__ float2 cand[4][SUP_CAP];
    __shared__ float  red[3][8];
    __shared__ int    wcnt[8];
    __shared__ float2 part[4][32];

    const int tid  = threadIdx.x;
    const int w    = tid >> 5;
    const int lane = tid & 31;
    const int rw   = w >> 1;                 // row within block 0..3
    const int h    = w & 1;                  // half 0/1
    const int grow = blockIdx.x * 4 + rw;    // global attention row
    const int z    = grow >> 10;             // (b,h)
    const int row  = grow & 1023;
    const int bb   = z >> 3, hh = z & 7;

    // ---- load 16 elements + local max ----
    const float4* r = (const float4*)(S + (size_t)grow * 1024) + h * 128;
    float y[16];
    float m = -3.4e38f;
#pragma unroll
    for (int wq = 0; wq < 4; wq++) {
        float4 v = r[wq * 32 + lane];
        y[wq * 4 + 0] = v.x; y[wq * 4 + 1] = v.y;
        y[wq * 4 + 2] = v.z; y[wq * 4 + 3] = v.w;
        m = fmaxf(m, fmaxf(fmaxf(v.x, v.y), fmaxf(v.z, v.w)));
    }
#pragma unroll
    for (int o = 16; o > 0; o >>= 1) m = fmaxf(m, __shfl_xor_sync(0xffffffffu, m, o));
    if (lane == 0) red[0][w] = m;
    __syncthreads();
    m = fmaxf(red[0][w], red[0][w ^ 1]);
    __syncthreads();

    // ---- 3 bisections: T* in [m-16, m] ----
    float lo = m - 16.f, hi = m;
#pragma unroll
    for (int it = 0; it < 3; it++) {
        float mid = 0.5f * (lo + hi);
        float s = 0.f;
#pragma unroll
        for (int j = 0; j < 16; j++) {
            float d = fmaxf(y[j] - mid, 0.f);
            s = fmaf(d, d, s);
        }
#pragma unroll
        for (int o = 16; o > 0; o >>= 1) s += __shfl_xor_sync(0xffffffffu, s, o);
        if (lane == 0) red[0][w] = s;
        __syncthreads();
        s = red[0][w] + red[0][w ^ 1];
        __syncthreads();
        if (s > 256.f) lo = mid; else hi = mid;
    }

    // ---- 2 Newton updates from the left bracket ----
    float t = lo;
#pragma unroll
    for (int it = 0; it < 2; it++) {
        float s1 = 0.f, s2 = 0.f;
#pragma unroll
        for (int j = 0; j < 16; j++) {
            float d = fmaxf(y[j] - t, 0.f);
            s1 += d;
            s2 = fmaf(d, d, s2);
        }
#pragma unroll
        for (int o = 16; o > 0; o >>= 1) {
            s1 += __shfl_xor_sync(0xffffffffu, s1, o);
            s2 += __shfl_xor_sync(0xffffffffu, s2, o);
        }
        if (lane == 0) { red[0][w] = s1; red[1][w] = s2; }
        __syncthreads();
        s1 = red[0][w] + red[0][w ^ 1];
        s2 = red[1][w] + red[1][w ^ 1];
        __syncthreads();
        t += (s2 - 256.f) / (2.f * s1);
    }

    // ---- final sums at t, closed form via transform ----
    float s1 = 0.f, s2 = 0.f, c = 0.f;
#pragma unroll
    for (int j = 0; j < 16; j++) {
        float d = y[j] - t;
        if (d > 0.f) { s1 += d; s2 = fmaf(d, d, s2); c += 1.f; }
    }
#pragma unroll
    for (int o = 16; o > 0; o >>= 1) {
        s1 += __shfl_xor_sync(0xffffffffu, s1, o);
        s2 += __shfl_xor_sync(0xffffffffu, s2, o);
        c  += __shfl_xor_sync(0xffffffffu, c,  o);
    }
    if (lane == 0) { red[0][w] = s1; red[1][w] = s2; red[2][w] = c; }
    __syncthreads();
    s1 = red[0][w] + red[0][w ^ 1];
    s2 = red[1][w] + red[1][w ^ 1];
    c  = red[2][w] + red[2][w ^ 1];
    __syncthreads();

    float SY   = s1 + c * t;
    float SY2  = s2 + 2.f * t * s1 + c * t * t;
    float disc = fmaxf(SY * SY - c * (SY2 - 256.f), 0.f);
    float T    = (SY - sqrtf(disc)) / c;

    // ---- compact support {y > T}: smem up to SUP_CAP, spill to Ovf ----
    int myc = 0;
#pragma unroll
    for (int j = 0; j < 16; j++)
        if (y[j] > T) myc++;

    int off = myc;
#pragma unroll
    for (int d = 1; d < 32; d <<= 1) {
        int n = __shfl_up_sync(0xffffffffu, off, d);
        if (lane >= d) off += n;
    }
    int wtot = __shfl_sync(0xffffffffu, off, 31);
    off -= myc;
    if (lane == 0) wcnt[w] = wtot;
    __syncthreads();
    const int base  = h ? wcnt[w ^ 1] : 0;
    const int total = wcnt[rw * 2] + wcnt[rw * 2 + 1];
    off += base;

    float2* ovf = Ovf + (size_t)grow * Sn;
    int wp = off;
#pragma unroll
    for (int j = 0; j < 16; j++) {
        if (y[j] > T) {
            float d = (y[j] - T) * 0.0625f;
            uint32_t pos = h * 512 + (j >> 2) * 128 + lane * 4 + (j & 3);
            float2 e = make_float2(d * d, __uint_as_float(pos));
            if (wp < SUP_CAP) cand[rw][wp] = e; else ovf[wp] = e;
            wp++;
        }
    }
    __syncthreads();

    // ---- gather: warps h=0/1 take interleaved entries, combine at end ----
    const float* V = qkv + (size_t)bb * Sn * D3 + 2 * Dn + hh * HD;
    float ax = 0.f, ay = 0.f, bx = 0.f, by = 0.f;
    int j = h;
    for (; j + 2 < total; j += 4) {
        float2 e0 = (j     < SUP_CAP) ? cand[rw][j]     : ovf[j];
        float2 e1 = (j + 2 < SUP_CAP) ? cand[rw][j + 2] : ovf[j + 2];
        const float2* v0 = (const float2*)(V + (size_t)__float_as_uint(e0.y) * D3);
        const float2* v1 = (const float2*)(V + (size_t)__float_as_uint(e1.y) * D3);
        float2 a = v0[lane], b = v1[lane];
        ax = fmaf(e0.x, a.x, ax); ay = fmaf(e0.x, a.y, ay);
        bx = fmaf(e1.x, b.x, bx); by = fmaf(e1.x, b.y, by);
    }
    if (j < total) {
        float2 e0 = (j < SUP_CAP) ? cand[rw][j] : ovf[j];
        const float2* v0 = (const float2*)(V + (size_t)__float_as_uint(e0.y) * D3);
        float2 a = v0[lane];
        ax = fmaf(e0.x, a.x, ax); ay = fmaf(e0.x, a.y, ay);
    }
    ax += bx; ay += by;

    if (h == 1) part[rw][lane] = make_float2(ax, ay);
    __syncthreads();
    if (h == 0) {
        float2 p = part[rw][lane];
        float2* cr = (float2*)(ctx + (size_t)(bb * Sn + row) * Dn + hh * HD);
        cr[lane] = make_float2(ax + p.x, ay + p.y);
    }
}

// ---------------------------------------------------------------------------
__device__ __forceinline__ float blkRedSum(float v, float* sm) {
#pragma unroll
    for (int o = 16; o > 0; o >>= 1) v += __shfl_xor_sync(0xffffffffu, v, o);
    int nw = blockDim.x >> 5;
    if ((threadIdx.x & 31) == 0) sm[threadIdx.x >> 5] = v;
    __syncthreads();
    if (threadIdx.x == 0) {
        float s = sm[0];
        for (int i = 1; i < nw; i++) s += sm[i];
        sm[0] = s;
    }
    __syncthreads();
    float r = sm[0];
    __syncthreads();
    return r;
}

// out = residual + LayerNorm(y) * g + b   (rows of 512, eps=1e-5, biased var)
__global__ __launch_bounds__(128)
void add_ln_kernel(const float* __restrict__ Y, const float* __restrict__ R,
                   const float* __restrict__ g, const float* __restrict__ b,
                   float* __restrict__ O)
{
    __shared__ float sm[4];
    size_t row = blockIdx.x;
    const float* y = Y + row * 512;
    int tid = threadIdx.x;

    float v[4];
#pragma unroll
    for (int j = 0; j < 4; j++) v[j] = y[tid + j * 128];
    float s = 0.f, ss = 0.f;
#pragma unroll
    for (int j = 0; j < 4; j++) { s += v[j]; ss = fmaf(v[j], v[j], ss); }
    s  = blkRedSum(s,  sm);
    ss = blkRedSum(ss, sm);
    float mean = s * (1.f / 512.f);
    float var  = ss * (1.f / 512.f) - mean * mean;
    float rstd = rsqrtf(var + 1e-5f);
#pragma unroll
    for (int j = 0; j < 4; j++) {
        int c = tid + j * 128;
        O[row * 512 + c] = R[row * 512 + c] + (v[j] - mean) * rstd * g[c] + b[c];
    }
}

// ---------------------------------------------------------------------------
extern "C" void kernel_launch(void* const* d_in, const int* in_sizes, int n_in,
                              void* d_out, int out_size)
{
    const float* x   = (const float*)d_in[0];
    const float* Wq  = (const float*)d_in[1];  const float* bq  = (const float*)d_in[2];
    const float* Wk  = (const float*)d_in[3];  const float* bk  = (const float*)d_in[4];
    const float* Wv  = (const float*)d_in[5];  const float* bv  = (const float*)d_in[6];
    const float* Wo  = (const float*)d_in[7];  const float* bo  = (const float*)d_in[8];
    const float* g1  = (const float*)d_in[9];  const float* be1 = (const float*)d_in[10];
    const float* W1  = (const float*)d_in[11]; const float* b1  = (const float*)d_in[12];
    const float* W2  = (const float*)d_in[13]; const float* b2  = (const float*)d_in[14];
    const float* g2  = (const float*)d_in[15]; const float* be2 = (const float*)d_in[16];
    float* out = (float*)d_out;

    float *qkv, *wcat, *bcat, *s, *ctx, *y, *x1, *h1, *y2;
    float2* ovf;
    cudaGetSymbolAddress((void**)&qkv,  gQKV);
    cudaGetSymbolAddress((void**)&wcat, gWcat);
    cudaGetSymbolAddress((void**)&bcat, gBcat);
    cudaGetSymbolAddress((void**)&s,    gS);
    cudaGetSymbolAddress((void**)&ovf,  gOvf);
    cudaGetSymbolAddress((void**)&ctx,  gCtx);
    cudaGetSymbolAddress((void**)&y,    gY);
    cudaGetSymbolAddress((void**)&x1,   gX1);
    cudaGetSymbolAddress((void**)&h1,   gH1);
    cudaGetSymbolAddress((void**)&y2,   gY2);

    const long long SD3 = (long long)Sn * D3;
    const long long SS  = (long long)Sn * Sn;

    // Opt in to >48KB dynamic smem for each instantiation
    constexpr size_t SM_BIG  = tg_smem_bytes(128, 128, 32, false);  // ~105 KB
    constexpr size_t SM_BIGT = tg_smem_bytes(128, 128, 32, true);   // ~108 KB
    cudaFuncSetAttribute((const void*)tgemm<128,128,32,64,32,EPI_BIAS,false>,
                         cudaFuncAttributeMaxDynamicSharedMemorySize, (int)SM_BIG);
    cudaFuncSetAttribute((const void*)tgemm<128,128,32,64,32,EPI_NONE,true>,
                         cudaFuncAttributeMaxDynamicSharedMemorySize, (int)SM_BIGT);
    cudaFuncSetAttribute((const void*)tgemm<128,128,32,64,32,EPI_MISH,false>,
                         cudaFuncAttributeMaxDynamicSharedMemorySize, (int)SM_BIG);

    // 0) pack QKV weights/biases
    concat_qkv<<<(Dn * Dn + 255) / 256, 256>>>(Wq, Wk, Wv, bq, bk, bv, wcat, bcat);

    // 1) QKV in one GEMM: [8192,512] @ [512,1536] + bias -> gQKV
    tgemm<128,128,32,64,32,EPI_BIAS,false>
        <<<dim3(D3 / 128, Mtok / 128, 1), 256, SM_BIG>>>(
        x, wcat, bcat, qkv, Mtok, D3, Dn, Dn, D3, D3, 0,0,0,0,0,0, 1);

    // 2) scores[b,h] = Q_h @ K_h^T (NT, K=64), batched over 64 (b,h)
    tgemm<128,128,32,64,32,EPI_NONE,true>
        <<<dim3(Sn / 128, Sn / 128, Bn * Hn), 256, SM_BIGT>>>(
        qkv, qkv + Dn, nullptr, s, Sn, Sn, HD, D3, D3, Sn,
        SD3, HD, SD3, HD, (long long)Hn * SS, SS, Hn);

    // 3+4) fused entmax tau solve + sparse P@V gather (2 warps per row)
    entmax_pv<<<NROWS / 4, 256>>>(s, qkv, ovf, ctx);

    // 5) y = ctx @ Wo + bo
    tgemm<128,128,32,64,32,EPI_BIAS,false>
        <<<dim3(Dn / 128, Mtok / 128, 1), 256, SM_BIG>>>(
        ctx, Wo, bo, y, Mtok, Dn, Dn, Dn, Dn, Dn, 0,0,0,0,0,0, 1);

    // 6) x1 = x + LN(y)
    add_ln_kernel<<<Mtok, 128>>>(y, x, g1, be1, x1);

    // 7) h1 = mish(x1 @ W1 + b1)  [8192,2048]
    tgemm<128,128,32,64,32,EPI_MISH,false>
        <<<dim3(Fn / 128, Mtok / 128, 1), 256, SM_BIG>>>(
        x1, W1, b1, h1, Mtok, Fn, Dn, Dn, Fn, Fn, 0,0,0,0,0,0, 1);

    // 8) y2 = h1 @ W2 + b2  [8192,512]
    tgemm<128,128,32,64,32,EPI_BIAS,false>
        <<<dim3(Dn / 128, Mtok / 128, 1), 256, SM_BIG>>>(
        h1, W2, b2, y2, Mtok, Dn, Fn, Fn, Dn, Dn, 0,0,0,0,0,0, 1);

    // 9) out = x1 + LN(y2)
    add_ln_kernel<<<Mtok, 128>>>(y2, x1, g2, be2, out);
}

// round 15
// speedup vs baseline: 1.0485x; 1.0485x over previous
#include <cuda_runtime.h>
#include <math.h>
#include <stdint.h>

// Problem constants
constexpr int Bn = 8, Sn = 1024, Dn = 512, Hn = 8, HD = 64, Fn = 2048;
constexpr int Mtok = Bn * Sn; // 8192
constexpr int D3 = 3 * Dn;    // 1536
constexpr int NROWS = Bn * Hn * Sn;   // 65536 attention rows

// Scratch (static device globals; no runtime allocation)
__device__ float  gQKV [(size_t)Mtok * D3];          // packed Q|K|V rows
__device__ float  gWcat[Dn * D3];
__device__ float  gBcat[D3];
__device__ float  gS   [(size_t)Bn * Hn * Sn * Sn];  // 256 MB raw scores
__device__ float2 gOvf [(size_t)NROWS * Sn];         // overflow spill (rarely touched)
__device__ float  gCtx [Mtok * Dn];
__device__ float  gY   [Mtok * Dn];
__device__ float  gX1  [Mtok * Dn];
__device__ float  gH1  [(size_t)Mtok * Fn];
__device__ float  gY2  [Mtok * Dn];

enum { EPI_NONE = 0, EPI_BIAS = 1, EPI_MISH = 2 };

// mish(x) = x*tanh(softplus(x)); with t=e^x, tanh(ln(1+t)) = (t^2+2t)/(t^2+2t+2)
__device__ __forceinline__ float mish_f(float v) {
    if (v > 20.f) return v;
    float t = __expf(v);
    float u = fmaf(t, t, 2.f * t);
    return __fdividef(v * u, u + 2.f);
}

__device__ __forceinline__ float to_tf32(float x) {
    float r;
    asm("cvt.rna.tf32.f32 %0, %1;" : "=f"(r) : "f"(x));
    return r;
}

__device__ __forceinline__ void cpa16(float* smem_dst, const float* gsrc) {
    uint32_t a = (uint32_t)__cvta_generic_to_shared(smem_dst);
    asm volatile("cp.async.cg.shared.global [%0], [%1], 16;" :: "r"(a), "l"(gsrc));
}
__device__ __forceinline__ void cp_commit() {
    asm volatile("cp.async.commit_group;");
}
template <int NN>
__device__ __forceinline__ void cp_wait() {
    asm volatile("cp.async.wait_group %0;" :: "n"(NN));
}

__device__ __forceinline__ void mma_tf32(float* acc, const uint32_t* a, const uint32_t* b) {
    asm volatile(
        "mma.sync.aligned.m16n8k8.row.col.f32.tf32.tf32.f32 "
        "{%0,%1,%2,%3}, {%4,%5,%6,%7}, {%8,%9}, {%0,%1,%2,%3};"
        : "+f"(acc[0]), "+f"(acc[1]), "+f"(acc[2]), "+f"(acc[3])
        : "r"(a[0]), "r"(a[1]), "r"(a[2]), "r"(a[3]), "r"(b[0]), "r"(b[1]));
}

// Host/device-consistent smem sizing (3-stage pipeline)
constexpr size_t tg_smem_bytes(int BM, int BN, int BK, bool BT) {
    int as = BM * (BK + 4);
    int bs = BT ? BN * (BK + 4) : BK * (BN + 8);
    return (size_t)(as + bs) * 3 * sizeof(float);
}

// ---------------------------------------------------------------------------
// tf32 tensor-core GEMM, 3-stage cp.async pipeline: C = A @ B (+bias)(+mish).
// BTRANS: B stored [N,K] (K contiguous) -> C = A @ B^T.
// ---------------------------------------------------------------------------
template <int BM, int BN, int BK, int WM, int WN, int EPI, bool BTRANS>
__global__ __launch_bounds__(256, 2)
void tgemm(const float* __restrict__ Ag, const float* __restrict__ Bg,
           const float* __restrict__ bias, float* __restrict__ Cg,
           int M, int N, int K, int lda, int ldb, int ldc,
           long long sA_b, long long sA_h,
           long long sB_b, long long sB_h,
           long long sC_b, long long sC_h, int Hdiv)
{
    constexpr int WARPS_N = BN / WN;
    constexpr int MI = WM / 16;
    constexpr int NI = WN / 8;
    constexpr int ASTR = BK + 4;
    constexpr int BNP  = BN + 8;
    constexpr int KQ   = BK / 4;             // 16B chunks per row
    constexpr int BS_ELEMS = BTRANS ? BN * ASTR : BK * BNP;

    extern __shared__ __align__(16) float dsm[];
    float* AsBase = dsm;                          // 3 * BM * ASTR
    float* BsBase = dsm + 3 * BM * ASTR;          // 3 * BS_ELEMS

    int z  = blockIdx.z;
    int bb = z / Hdiv, hh = z - bb * Hdiv;
    const float* A = Ag + (size_t)bb * sA_b + (size_t)hh * sA_h;
    const float* B = Bg + (size_t)bb * sB_b + (size_t)hh * sB_h;
    float*       C = Cg + (size_t)bb * sC_b + (size_t)hh * sC_h;

    const int tid  = threadIdx.x;
    const int lane = tid & 31;
    const int w    = tid >> 5;
    const int gid  = lane >> 2;   // 0..7
    const int tig  = lane & 3;    // 0..3
    const int wm0  = (w / WARPS_N) * WM;
    const int wn0  = (w % WARPS_N) * WN;
    const int m0   = blockIdx.y * BM;
    const int n0   = blockIdx.x * BN;

    float acc[MI][NI][4];
#pragma unroll
    for (int i = 0; i < MI; i++)
#pragma unroll
        for (int j = 0; j < NI; j++)
#pragma unroll
            for (int c = 0; c < 4; c++) acc[i][j][c] = 0.f;

    const int nTiles = K / BK;

    auto load_tile = [&](int kt, int buf) {
        float* As = AsBase + buf * (BM * ASTR);
        float* Bs = BsBase + buf * BS_ELEMS;
#pragma unroll
        for (int i = tid; i < BM * KQ; i += 256) {
            int m = i / KQ, kc = (i % KQ) * 4;
            cpa16(&As[m * ASTR + kc], A + (size_t)(m0 + m) * lda + kt * BK + kc);
        }
        if (BTRANS) {
#pragma unroll
            for (int i = tid; i < BN * KQ; i += 256) {
                int n = i / KQ, kc = (i % KQ) * 4;
                cpa16(&Bs[n * ASTR + kc], B + (size_t)(n0 + n) * ldb + kt * BK + kc);
            }
        } else {
#pragma unroll
            for (int i = tid; i < BK * BN / 4; i += 256) {
                int kr = i / (BN / 4), nq = (i % (BN / 4)) * 4;
                cpa16(&Bs[kr * BNP + nq], B + (size_t)(kt * BK + kr) * ldb + n0 + nq);
            }
        }
        cp_commit();
    };

    load_tile(0, 0);
    load_tile(1, 1);

    for (int kt = 0; kt < nTiles; kt++) {
        if (kt + 1 >= nTiles) cp_wait<0>(); else cp_wait<1>();
        __syncthreads();
        if (kt + 2 < nTiles) load_tile(kt + 2, (kt + 2) % 3);

        int buf = kt % 3;
        const float* As = AsBase + buf * (BM * ASTR);
        const float* Bs = BsBase + buf * BS_ELEMS;

#pragma unroll
        for (int ks = 0; ks < BK; ks += 8) {
            uint32_t af[MI][4], bf[NI][2];
#pragma unroll
            for (int mi = 0; mi < MI; mi++) {
                const float* ap = As + (wm0 + mi * 16 + gid) * ASTR + ks + tig;
                af[mi][0] = __float_as_uint(to_tf32(ap[0]));
                af[mi][1] = __float_as_uint(to_tf32(ap[8 * ASTR]));
                af[mi][2] = __float_as_uint(to_tf32(ap[4]));
                af[mi][3] = __float_as_uint(to_tf32(ap[8 * ASTR + 4]));
            }
#pragma unroll
            for (int ni = 0; ni < NI; ni++) {
                if (BTRANS) {
                    const float* bp = Bs + (wn0 + ni * 8 + gid) * ASTR + ks + tig;
                    bf[ni][0] = __float_as_uint(to_tf32(bp[0]));
                    bf[ni][1] = __float_as_uint(to_tf32(bp[4]));
                } else {
                    const float* bp = Bs + (ks + tig) * BNP + wn0 + ni * 8 + gid;
                    bf[ni][0] = __float_as_uint(to_tf32(bp[0]));
                    bf[ni][1] = __float_as_uint(to_tf32(bp[4 * BNP]));
                }
            }
#pragma unroll
            for (int mi = 0; mi < MI; mi++)
#pragma unroll
                for (int ni = 0; ni < NI; ni++)
                    mma_tf32(acc[mi][ni], af[mi], bf[ni]);
        }
    }

    // --- Epilogue ---
#pragma unroll
    for (int mi = 0; mi < MI; mi++) {
#pragma unroll
        for (int ni = 0; ni < NI; ni++) {
            int row = m0 + wm0 + mi * 16 + gid;
            int col = n0 + wn0 + ni * 8 + tig * 2;
            float b0 = 0.f, b1 = 0.f;
            if (EPI >= 1) { b0 = bias[col]; b1 = bias[col + 1]; }
            float v0 = acc[mi][ni][0] + b0, v1 = acc[mi][ni][1] + b1;
            float v2 = acc[mi][ni][2] + b0, v3 = acc[mi][ni][3] + b1;
            if (EPI == 2) { v0 = mish_f(v0); v1 = mish_f(v1); v2 = mish_f(v2); v3 = mish_f(v3); }
            *(float2*)(C + (size_t)row * ldc + col)       = make_float2(v0, v1);
            *(float2*)(C + (size_t)(row + 8) * ldc + col) = make_float2(v2, v3);
        }
    }
}

// ---------------------------------------------------------------------------
// Pack Wq|Wk|Wv -> gWcat [512][1536], biases -> gBcat [1536]
// ---------------------------------------------------------------------------
__global__ __launch_bounds__(256)
void concat_qkv(const float* __restrict__ Wq, const float* __restrict__ Wk,
                const float* __restrict__ Wv,
                const float* __restrict__ bq, const float* __restrict__ bk,
                const float* __restrict__ bv,
                float* __restrict__ Wcat, float* __restrict__ bcat)
{
    int i = blockIdx.x * 256 + threadIdx.x;
    if (i < Dn * Dn) {
        int k = i >> 9, n = i & 511;
        Wcat[k * D3 + n]          = Wq[i];
        Wcat[k * D3 + Dn + n]     = Wk[i];
        Wcat[k * D3 + 2 * Dn + n] = Wv[i];
    }
    if (i < Dn) {
        bcat[i]          = bq[i];
        bcat[Dn + i]     = bk[i];
        bcat[2 * Dn + i] = bv[i];
    }
}

// ---------------------------------------------------------------------------
// Fused entmax-1.5 + sparse attn@V, warp per attention row.
// Phase A: raw-domain tau solve from registers (max fused into load,
//          2 bisect, 2 Newton updates, final sums pass + closed-form via
//          the transform SY = s1 + c*t, SY2 = s2 + 2t*s1 + c*t^2).
//          After 2 bisects the bracket is 4 raw-units; two Newton steps
//          (contraction ~0.125) leave |T*-t| ~ 0.06, so misincluded
//          closed-form elements carry weight <= (0.06/16)^2 ~ 1.5e-5.
// Phase B: compact support {y > T} into smem (cap 128; global spill).
// Phase C: gather ctx[row,:] = sum p_j * V[idx_j,:] (fp32, 4-way unroll).
// ---------------------------------------------------------------------------
constexpr int SUP_CAP = 128;

__global__ __launch_bounds__(256)
void entmax_pv(const float* __restrict__ S, const float* __restrict__ qkv,
               float2* __restrict__ Ovf, float* __restrict__ ctx)
{
    __shared__ float2 cand[8][SUP_CAP];

    const int w    = threadIdx.x >> 5;
    const int lane = threadIdx.x & 31;
    const int grow = blockIdx.x * 8 + w;         // global row
    const int z    = grow >> 10;                 // (b,h)
    const int row  = grow & 1023;
    const int bb   = z >> 3, hh = z & 7;

    // ---- load row + max ----
    const float4* r = (const float4*)(S + (size_t)grow * 1024);
    float y[32];
    float m = -3.4e38f;
#pragma unroll
    for (int wq = 0; wq < 8; wq++) {
        float4 v = r[wq * 32 + lane];
        y[wq * 4 + 0] = v.x; y[wq * 4 + 1] = v.y;
        y[wq * 4 + 2] = v.z; y[wq * 4 + 3] = v.w;
        m = fmaxf(m, fmaxf(fmaxf(v.x, v.y), fmaxf(v.z, v.w)));
    }
#pragma unroll
    for (int o = 16; o > 0; o >>= 1) m = fmaxf(m, __shfl_xor_sync(0xffffffffu, m, o));

    // ---- 2 bisections: T* in [m-16, m], f(lo) >= 256 invariant ----
    float lo = m - 16.f, hi = m;
#pragma unroll
    for (int it = 0; it < 2; it++) {
        float mid = 0.5f * (lo + hi);
        float sa = 0.f, sb = 0.f;
#pragma unroll
        for (int j = 0; j < 32; j += 2) {
            float d0 = fmaxf(y[j]     - mid, 0.f);
            float d1 = fmaxf(y[j + 1] - mid, 0.f);
            sa = fmaf(d0, d0, sa);
            sb = fmaf(d1, d1, sb);
        }
        float s = sa + sb;
#pragma unroll
        for (int o = 16; o > 0; o >>= 1) s += __shfl_xor_sync(0xffffffffu, s, o);
        if (s > 256.f) lo = mid; else hi = mid;
    }

    // ---- 2 Newton updates from the left bracket ----
    float t = lo;
#pragma unroll
    for (int it = 0; it < 2; it++) {
        float s1 = 0.f, s2a = 0.f, s2b = 0.f;
#pragma unroll
        for (int j = 0; j < 32; j += 2) {
            float d0 = fmaxf(y[j]     - t, 0.f);
            float d1 = fmaxf(y[j + 1] - t, 0.f);
            s1 += d0 + d1;
            s2a = fmaf(d0, d0, s2a);
            s2b = fmaf(d1, d1, s2b);
        }
        float s2 = s2a + s2b;
#pragma unroll
        for (int o = 16; o > 0; o >>= 1) {
            s1 += __shfl_xor_sync(0xffffffffu, s1, o);
            s2 += __shfl_xor_sync(0xffffffffu, s2, o);
        }
        t += (s2 - 256.f) / (2.f * s1);
    }

    // ---- final sums at t (close to T*), closed form via transform ----
    float s1 = 0.f, s2 = 0.f, c = 0.f;
#pragma unroll
    for (int j = 0; j < 32; j++) {
        float d = y[j] - t;
        if (d > 0.f) { s1 += d; s2 = fmaf(d, d, s2); c += 1.f; }
    }
#pragma unroll
    for (int o = 16; o > 0; o >>= 1) {
        s1 += __shfl_xor_sync(0xffffffffu, s1, o);
        s2 += __shfl_xor_sync(0xffffffffu, s2, o);
        c  += __shfl_xor_sync(0xffffffffu, c,  o);
    }
    float SY   = s1 + c * t;
    float SY2  = s2 + 2.f * t * s1 + c * t * t;
    float disc = fmaxf(SY * SY - c * (SY2 - 256.f), 0.f);
    float T    = (SY - sqrtf(disc)) / c;

    // ---- compact support {y > T}: smem up to SUP_CAP, spill to Ovf ----
    int myc = 0;
#pragma unroll
    for (int j = 0; j < 32; j++)
        if (y[j] > T) myc++;

    int off = myc;
#pragma unroll
    for (int d = 1; d < 32; d <<= 1) {
        int n = __shfl_up_sync(0xffffffffu, off, d);
        if (lane >= d) off += n;
    }
    int total = __shfl_sync(0xffffffffu, off, 31);
    off -= myc;

    float2* ovf = Ovf + (size_t)grow * Sn;
    int wp = off;
#pragma unroll
    for (int j = 0; j < 32; j++) {
        if (y[j] > T) {
            float d = (y[j] - T) * 0.0625f;
            uint32_t pos = ((j >> 2) << 7) + (lane << 2) + (j & 3);
            float2 e = make_float2(d * d, __uint_as_float(pos));
            if (wp < SUP_CAP) cand[w][wp] = e; else ovf[wp] = e;
            wp++;
        }
    }
    __syncwarp();

    // ---- gather: ctx[row,:] = sum p_j * V[idx_j,:] (4-way unrolled) ----
    const float* V = qkv + (size_t)bb * Sn * D3 + 2 * Dn + hh * HD;
    const int nsm = total < SUP_CAP ? total : SUP_CAP;

    float ax = 0.f, ay = 0.f, bx = 0.f, by = 0.f;
    float cx = 0.f, cy = 0.f, dx = 0.f, dy = 0.f;
    int j = 0;
    for (; j + 4 <= nsm; j += 4) {
        float2 e0 = cand[w][j],     e1 = cand[w][j + 1];
        float2 e2 = cand[w][j + 2], e3 = cand[w][j + 3];
        const float2* v0 = (const float2*)(V + (size_t)__float_as_uint(e0.y) * D3);
        const float2* v1 = (const float2*)(V + (size_t)__float_as_uint(e1.y) * D3);
        const float2* v2 = (const float2*)(V + (size_t)__float_as_uint(e2.y) * D3);
        const float2* v3 = (const float2*)(V + (size_t)__float_as_uint(e3.y) * D3);
        float2 a = v0[lane], b = v1[lane], cc = v2[lane], dd = v3[lane];
        ax = fmaf(e0.x, a.x,  ax); ay = fmaf(e0.x, a.y,  ay);
        bx = fmaf(e1.x, b.x,  bx); by = fmaf(e1.x, b.y,  by);
        cx = fmaf(e2.x, cc.x, cx); cy = fmaf(e2.x, cc.y, cy);
        dx = fmaf(e3.x, dd.x, dx); dy = fmaf(e3.x, dd.y, dy);
    }
    for (; j < nsm; j++) {
        float2 e0 = cand[w][j];
        const float2* v0 = (const float2*)(V + (size_t)__float_as_uint(e0.y) * D3);
        float2 a = v0[lane];
        ax = fmaf(e0.x, a.x, ax); ay = fmaf(e0.x, a.y, ay);
    }
    for (; j < total; j++) {         // overflow tail (rare)
        float2 e0 = ovf[j];
        const float2* v0 = (const float2*)(V + (size_t)__float_as_uint(e0.y) * D3);
        float2 a = v0[lane];
        ax = fmaf(e0.x, a.x, ax); ay = fmaf(e0.x, a.y, ay);
    }

    float2* cr = (float2*)(ctx + (size_t)(bb * Sn + row) * Dn + hh * HD);
    cr[lane] = make_float2((ax + bx) + (cx + dx), (ay + by) + (cy + dy));
}

// ---------------------------------------------------------------------------
__device__ __forceinline__ float blkRedSum(float v, float* sm) {
#pragma unroll
    for (int o = 16; o > 0; o >>= 1) v += __shfl_xor_sync(0xffffffffu, v, o);
    int nw = blockDim.x >> 5;
    if ((threadIdx.x & 31) == 0) sm[threadIdx.x >> 5] = v;
    __syncthreads();
    if (threadIdx.x == 0) {
        float s = sm[0];
        for (int i = 1; i < nw; i++) s += sm[i];
        sm[0] = s;
    }
    __syncthreads();
    float r = sm[0];
    __syncthreads();
    return r;
}

// out = residual + LayerNorm(y) * g + b   (rows of 512, eps=1e-5, biased var)
__global__ __launch_bounds__(128)
void add_ln_kernel(const float* __restrict__ Y, const float* __restrict__ R,
                   const float* __restrict__ g, const float* __restrict__ b,
                   float* __restrict__ O)
{
    __shared__ float sm[4];
    size_t row = blockIdx.x;
    const float* y = Y + row * 512;
    int tid = threadIdx.x;

    float v[4];
#pragma unroll
    for (int j = 0; j < 4; j++) v[j] = y[tid + j * 128];
    float s = 0.f, ss = 0.f;
#pragma unroll
    for (int j = 0; j < 4; j++) { s += v[j]; ss = fmaf(v[j], v[j], ss); }
    s  = blkRedSum(s,  sm);
    ss = blkRedSum(ss, sm);
    float mean = s * (1.f / 512.f);
    float var  = ss * (1.f / 512.f) - mean * mean;
    float rstd = rsqrtf(var + 1e-5f);
#pragma unroll
    for (int j = 0; j < 4; j++) {
        int c = tid + j * 128;
        O[row * 512 + c] = R[row * 512 + c] + (v[j] - mean) * rstd * g[c] + b[c];
    }
}

// ---------------------------------------------------------------------------
extern "C" void kernel_launch(void* const* d_in, const int* in_sizes, int n_in,
                              void* d_out, int out_size)
{
    const float* x   = (const float*)d_in[0];
    const float* Wq  = (const float*)d_in[1];  const float* bq  = (const float*)d_in[2];
    const float* Wk  = (const float*)d_in[3];  const float* bk  = (const float*)d_in[4];
    const float* Wv  = (const float*)d_in[5];  const float* bv  = (const float*)d_in[6];
    const float* Wo  = (const float*)d_in[7];  const float* bo  = (const float*)d_in[8];
    const float* g1  = (const float*)d_in[9];  const float* be1 = (const float*)d_in[10];
    const float* W1  = (const float*)d_in[11]; const float* b1  = (const float*)d_in[12];
    const float* W2  = (const float*)d_in[13]; const float* b2  = (const float*)d_in[14];
    const float* g2  = (const float*)d_in[15]; const float* be2 = (const float*)d_in[16];
    float* out = (float*)d_out;

    float *qkv, *wcat, *bcat, *s, *ctx, *y, *x1, *h1, *y2;
    float2* ovf;
    cudaGetSymbolAddress((void**)&qkv,  gQKV);
    cudaGetSymbolAddress((void**)&wcat, gWcat);
    cudaGetSymbolAddress((void**)&bcat, gBcat);
    cudaGetSymbolAddress((void**)&s,    gS);
    cudaGetSymbolAddress((void**)&ovf,  gOvf);
    cudaGetSymbolAddress((void**)&ctx,  gCtx);
    cudaGetSymbolAddress((void**)&y,    gY);
    cudaGetSymbolAddress((void**)&x1,   gX1);
    cudaGetSymbolAddress((void**)&h1,   gH1);
    cudaGetSymbolAddress((void**)&y2,   gY2);

    const long long SD3 = (long long)Sn * D3;
    const long long SS  = (long long)Sn * Sn;

    // Opt in to >48KB dynamic smem for each instantiation
    constexpr size_t SM_BIG  = tg_smem_bytes(128, 128, 32, false);  // ~105 KB
    constexpr size_t SM_BIGT = tg_smem_bytes(128, 128, 32, true);   // ~108 KB
    cudaFuncSetAttribute((const void*)tgemm<128,128,32,64,32,EPI_BIAS,false>,
                         cudaFuncAttributeMaxDynamicSharedMemorySize, (int)SM_BIG);
    cudaFuncSetAttribute((const void*)tgemm<128,128,32,64,32,EPI_NONE,true>,
                         cudaFuncAttributeMaxDynamicSharedMemorySize, (int)SM_BIGT);
    cudaFuncSetAttribute((const void*)tgemm<128,128,32,64,32,EPI_MISH,false>,
                         cudaFuncAttributeMaxDynamicSharedMemorySize, (int)SM_BIG);

    // 0) pack QKV weights/biases
    concat_qkv<<<(Dn * Dn + 255) / 256, 256>>>(Wq, Wk, Wv, bq, bk, bv, wcat, bcat);

    // 1) QKV in one GEMM: [8192,512] @ [512,1536] + bias -> gQKV
    tgemm<128,128,32,64,32,EPI_BIAS,false>
        <<<dim3(D3 / 128, Mtok / 128, 1), 256, SM_BIG>>>(
        x, wcat, bcat, qkv, Mtok, D3, Dn, Dn, D3, D3, 0,0,0,0,0,0, 1);

    // 2) scores[b,h] = Q_h @ K_h^T (NT, K=64), batched over 64 (b,h)
    tgemm<128,128,32,64,32,EPI_NONE,true>
        <<<dim3(Sn / 128, Sn / 128, Bn * Hn), 256, SM_BIGT>>>(
        qkv, qkv + Dn, nullptr, s, Sn, Sn, HD, D3, D3, Sn,
        SD3, HD, SD3, HD, (long long)Hn * SS, SS, Hn);

    // 3+4) fused entmax tau solve + sparse P@V gather (warp per row)
    entmax_pv<<<NROWS / 8, 256>>>(s, qkv, ovf, ctx);

    // 5) y = ctx @ Wo + bo
    tgemm<128,128,32,64,32,EPI_BIAS,false>
        <<<dim3(Dn / 128, Mtok / 128, 1), 256, SM_BIG>>>(
        ctx, Wo, bo, y, Mtok, Dn, Dn, Dn, Dn, Dn, 0,0,0,0,0,0, 1);

    // 6) x1 = x + LN(y)
    add_ln_kernel<<<Mtok, 128>>>(y, x, g1, be1, x1);

    // 7) h1 = mish(x1 @ W1 + b1)  [8192,2048]
    tgemm<128,128,32,64,32,EPI_MISH,false>
        <<<dim3(Fn / 128, Mtok / 128, 1), 256, SM_BIG>>>(
        x1, W1, b1, h1, Mtok, Fn, Dn, Dn, Fn, Fn, 0,0,0,0,0,0, 1);

    // 8) y2 = h1 @ W2 + b2  [8192,512]
    tgemm<128,128,32,64,32,EPI_BIAS,false>
        <<<dim3(Dn / 128, Mtok / 128, 1), 256, SM_BIG>>>(
        h1, W2, b2, y2, Mtok, Dn, Fn, Fn, Dn, Dn, 0,0,0,0,0,0, 1);

    // 9) out = x1 + LN(y2)
    add_ln_kernel<<<Mtok, 128>>>(y2, x1, g2, be2, out);
}

// round 16
// speedup vs baseline: 1.0620x; 1.0129x over previous
#include <cuda_runtime.h>
#include <math.h>
#include <stdint.h>

// Problem constants
constexpr int Bn = 8, Sn = 1024, Dn = 512, Hn = 8, HD = 64, Fn = 2048;
constexpr int Mtok = Bn * Sn; // 8192
constexpr int D3 = 3 * Dn;    // 1536
constexpr int NROWS = Bn * Hn * Sn;   // 65536 attention rows

// Scratch (static device globals; no runtime allocation)
__device__ float  gQKV [(size_t)Mtok * D3];          // packed Q|K|V rows
__device__ float  gWcat[Dn * D3];
__device__ float  gBcat[D3];
__device__ float  gS   [(size_t)Bn * Hn * Sn * Sn];  // 256 MB raw scores
__device__ float2 gOvf [(size_t)NROWS * Sn];         // overflow spill (rarely touched)
__device__ float  gCtx [Mtok * Dn];
__device__ float  gY   [Mtok * Dn];
__device__ float  gX1  [Mtok * Dn];
__device__ float  gH1  [(size_t)Mtok * Fn];
__device__ float  gY2  [Mtok * Dn];

enum { EPI_NONE = 0, EPI_BIAS = 1, EPI_MISH = 2 };

// mish(x) = x*tanh(softplus(x)); with t=e^x, tanh(ln(1+t)) = (t^2+2t)/(t^2+2t+2)
__device__ __forceinline__ float mish_f(float v) {
    if (v > 20.f) return v;
    float t = __expf(v);
    float u = fmaf(t, t, 2.f * t);
    return __fdividef(v * u, u + 2.f);
}

__device__ __forceinline__ float to_tf32(float x) {
    float r;
    asm("cvt.rna.tf32.f32 %0, %1;" : "=f"(r) : "f"(x));
    return r;
}

__device__ __forceinline__ void cpa16(float* smem_dst, const float* gsrc) {
    uint32_t a = (uint32_t)__cvta_generic_to_shared(smem_dst);
    asm volatile("cp.async.cg.shared.global [%0], [%1], 16;" :: "r"(a), "l"(gsrc));
}
__device__ __forceinline__ void cp_commit() {
    asm volatile("cp.async.commit_group;");
}
template <int NN>
__device__ __forceinline__ void cp_wait() {
    asm volatile("cp.async.wait_group %0;" :: "n"(NN));
}

__device__ __forceinline__ void mma_tf32(float* acc, const uint32_t* a, const uint32_t* b) {
    asm volatile(
        "mma.sync.aligned.m16n8k8.row.col.f32.tf32.tf32.f32 "
        "{%0,%1,%2,%3}, {%4,%5,%6,%7}, {%8,%9}, {%0,%1,%2,%3};"
        : "+f"(acc[0]), "+f"(acc[1]), "+f"(acc[2]), "+f"(acc[3])
        : "r"(a[0]), "r"(a[1]), "r"(a[2]), "r"(a[3]), "r"(b[0]), "r"(b[1]));
}

// Host/device-consistent smem sizing (3-stage pipeline)
constexpr size_t tg_smem_bytes(int BM, int BN, int BK, bool BT) {
    int as = BM * (BK + 4);
    int bs = BT ? BN * (BK + 4) : BK * (BN + 8);
    return (size_t)(as + bs) * 3 * sizeof(float);
}

// ---------------------------------------------------------------------------
// tf32 tensor-core GEMM, 3-stage cp.async pipeline: C = A @ B (+bias)(+mish).
// BTRANS: B stored [N,K] (K contiguous) -> C = A @ B^T.
// ---------------------------------------------------------------------------
template <int BM, int BN, int BK, int WM, int WN, int EPI, bool BTRANS>
__global__ __launch_bounds__(256, 2)
void tgemm(const float* __restrict__ Ag, const float* __restrict__ Bg,
           const float* __restrict__ bias, float* __restrict__ Cg,
           int M, int N, int K, int lda, int ldb, int ldc,
           long long sA_b, long long sA_h,
           long long sB_b, long long sB_h,
           long long sC_b, long long sC_h, int Hdiv)
{
    constexpr int WARPS_N = BN / WN;
    constexpr int MI = WM / 16;
    constexpr int NI = WN / 8;
    constexpr int ASTR = BK + 4;
    constexpr int BNP  = BN + 8;
    constexpr int KQ   = BK / 4;             // 16B chunks per row
    constexpr int BS_ELEMS = BTRANS ? BN * ASTR : BK * BNP;

    extern __shared__ __align__(16) float dsm[];
    float* AsBase = dsm;                          // 3 * BM * ASTR
    float* BsBase = dsm + 3 * BM * ASTR;          // 3 * BS_ELEMS

    int z  = blockIdx.z;
    int bb = z / Hdiv, hh = z - bb * Hdiv;
    const float* A = Ag + (size_t)bb * sA_b + (size_t)hh * sA_h;
    const float* B = Bg + (size_t)bb * sB_b + (size_t)hh * sB_h;
    float*       C = Cg + (size_t)bb * sC_b + (size_t)hh * sC_h;

    const int tid  = threadIdx.x;
    const int lane = tid & 31;
    const int w    = tid >> 5;
    const int gid  = lane >> 2;   // 0..7
    const int tig  = lane & 3;    // 0..3
    const int wm0  = (w / WARPS_N) * WM;
    const int wn0  = (w % WARPS_N) * WN;
    const int m0   = blockIdx.y * BM;
    const int n0   = blockIdx.x * BN;

    float acc[MI][NI][4];
#pragma unroll
    for (int i = 0; i < MI; i++)
#pragma unroll
        for (int j = 0; j < NI; j++)
#pragma unroll
            for (int c = 0; c < 4; c++) acc[i][j][c] = 0.f;

    const int nTiles = K / BK;

    auto load_tile = [&](int kt, int buf) {
        float* As = AsBase + buf * (BM * ASTR);
        float* Bs = BsBase + buf * BS_ELEMS;
#pragma unroll
        for (int i = tid; i < BM * KQ; i += 256) {
            int m = i / KQ, kc = (i % KQ) * 4;
            cpa16(&As[m * ASTR + kc], A + (size_t)(m0 + m) * lda + kt * BK + kc);
        }
        if (BTRANS) {
#pragma unroll
            for (int i = tid; i < BN * KQ; i += 256) {
                int n = i / KQ, kc = (i % KQ) * 4;
                cpa16(&Bs[n * ASTR + kc], B + (size_t)(n0 + n) * ldb + kt * BK + kc);
            }
        } else {
#pragma unroll
            for (int i = tid; i < BK * BN / 4; i += 256) {
                int kr = i / (BN / 4), nq = (i % (BN / 4)) * 4;
                cpa16(&Bs[kr * BNP + nq], B + (size_t)(kt * BK + kr) * ldb + n0 + nq);
            }
        }
        cp_commit();
    };

    load_tile(0, 0);
    load_tile(1, 1);

    for (int kt = 0; kt < nTiles; kt++) {
        if (kt + 1 >= nTiles) cp_wait<0>(); else cp_wait<1>();
        __syncthreads();
        if (kt + 2 < nTiles) load_tile(kt + 2, (kt + 2) % 3);

        int buf = kt % 3;
        const float* As = AsBase + buf * (BM * ASTR);
        const float* Bs = BsBase + buf * BS_ELEMS;

#pragma unroll
        for (int ks = 0; ks < BK; ks += 8) {
            uint32_t af[MI][4], bf[NI][2];
#pragma unroll
            for (int mi = 0; mi < MI; mi++) {
                const float* ap = As + (wm0 + mi * 16 + gid) * ASTR + ks + tig;
                af[mi][0] = __float_as_uint(to_tf32(ap[0]));
                af[mi][1] = __float_as_uint(to_tf32(ap[8 * ASTR]));
                af[mi][2] = __float_as_uint(to_tf32(ap[4]));
                af[mi][3] = __float_as_uint(to_tf32(ap[8 * ASTR + 4]));
            }
#pragma unroll
            for (int ni = 0; ni < NI; ni++) {
                if (BTRANS) {
                    const float* bp = Bs + (wn0 + ni * 8 + gid) * ASTR + ks + tig;
                    bf[ni][0] = __float_as_uint(to_tf32(bp[0]));
                    bf[ni][1] = __float_as_uint(to_tf32(bp[4]));
                } else {
                    const float* bp = Bs + (ks + tig) * BNP + wn0 + ni * 8 + gid;
                    bf[ni][0] = __float_as_uint(to_tf32(bp[0]));
                    bf[ni][1] = __float_as_uint(to_tf32(bp[4 * BNP]));
                }
            }
#pragma unroll
            for (int mi = 0; mi < MI; mi++)
#pragma unroll
                for (int ni = 0; ni < NI; ni++)
                    mma_tf32(acc[mi][ni], af[mi], bf[ni]);
        }
    }

    // --- Epilogue ---
#pragma unroll
    for (int mi = 0; mi < MI; mi++) {
#pragma unroll
        for (int ni = 0; ni < NI; ni++) {
            int row = m0 + wm0 + mi * 16 + gid;
            int col = n0 + wn0 + ni * 8 + tig * 2;
            float b0 = 0.f, b1 = 0.f;
            if (EPI >= 1) { b0 = bias[col]; b1 = bias[col + 1]; }
            float v0 = acc[mi][ni][0] + b0, v1 = acc[mi][ni][1] + b1;
            float v2 = acc[mi][ni][2] + b0, v3 = acc[mi][ni][3] + b1;
            if (EPI == 2) { v0 = mish_f(v0); v1 = mish_f(v1); v2 = mish_f(v2); v3 = mish_f(v3); }
            *(float2*)(C + (size_t)row * ldc + col)       = make_float2(v0, v1);
            *(float2*)(C + (size_t)(row + 8) * ldc + col) = make_float2(v2, v3);
        }
    }
}

// ---------------------------------------------------------------------------
// Pack Wq|Wk|Wv -> gWcat [512][1536], biases -> gBcat [1536]
// ---------------------------------------------------------------------------
__global__ __launch_bounds__(256)
void concat_qkv(const float* __restrict__ Wq, const float* __restrict__ Wk,
                const float* __restrict__ Wv,
                const float* __restrict__ bq, const float* __restrict__ bk,
                const float* __restrict__ bv,
                float* __restrict__ Wcat, float* __restrict__ bcat)
{
    int i = blockIdx.x * 256 + threadIdx.x;
    if (i < Dn * Dn) {
        int k = i >> 9, n = i & 511;
        Wcat[k * D3 + n]          = Wq[i];
        Wcat[k * D3 + Dn + n]     = Wk[i];
        Wcat[k * D3 + 2 * Dn + n] = Wv[i];
    }
    if (i < Dn) {
        bcat[i]          = bq[i];
        bcat[Dn + i]     = bk[i];
        bcat[2 * Dn + i] = bv[i];
    }
}

// ---------------------------------------------------------------------------
// Fused entmax-1.5 + sparse attn@V, warp per attention row.
// Phase A: raw-domain tau solve from registers (max fused into load,
//          3 bisect, 2 Newton updates, final sums pass + closed-form via
//          the transform SY = s1 + c*t, SY2 = s2 + 2t*s1 + c*t^2).
// Phase B: compact support {y > T} into smem (cap 128; global spill).
// Phase C: gather ctx[row,:] = sum p_j * V[idx_j,:] (fp32, 4-way unroll).
// __launch_bounds__(256, 4): cap at 64 regs -> 4 CTAs/SM (occupancy over
// the few spilled registers; kernel is memory-latency-bound at 3 CTAs).
// ---------------------------------------------------------------------------
constexpr int SUP_CAP = 128;

__global__ __launch_bounds__(256, 4)
void entmax_pv(const float* __restrict__ S, const float* __restrict__ qkv,
               float2* __restrict__ Ovf, float* __restrict__ ctx)
{
    __shared__ float2 cand[8][SUP_CAP];

    const int w    = threadIdx.x >> 5;
    const int lane = threadIdx.x & 31;
    const int grow = blockIdx.x * 8 + w;         // global row
    const int z    = grow >> 10;                 // (b,h)
    const int row  = grow & 1023;
    const int bb   = z >> 3, hh = z & 7;

    // ---- load row + max ----
    const float4* r = (const float4*)(S + (size_t)grow * 1024);
    float y[32];
    float m = -3.4e38f;
#pragma unroll
    for (int wq = 0; wq < 8; wq++) {
        float4 v = r[wq * 32 + lane];
        y[wq * 4 + 0] = v.x; y[wq * 4 + 1] = v.y;
        y[wq * 4 + 2] = v.z; y[wq * 4 + 3] = v.w;
        m = fmaxf(m, fmaxf(fmaxf(v.x, v.y), fmaxf(v.z, v.w)));
    }
#pragma unroll
    for (int o = 16; o > 0; o >>= 1) m = fmaxf(m, __shfl_xor_sync(0xffffffffu, m, o));

    // ---- 3 bisections: T* in [m-16, m], f(lo) >= 256 invariant ----
    float lo = m - 16.f, hi = m;
#pragma unroll
    for (int it = 0; it < 3; it++) {
        float mid = 0.5f * (lo + hi);
        float sa = 0.f, sb = 0.f;
#pragma unroll
        for (int j = 0; j < 32; j += 2) {
            float d0 = fmaxf(y[j]     - mid, 0.f);
            float d1 = fmaxf(y[j + 1] - mid, 0.f);
            sa = fmaf(d0, d0, sa);
            sb = fmaf(d1, d1, sb);
        }
        float s = sa + sb;
#pragma unroll
        for (int o = 16; o > 0; o >>= 1) s += __shfl_xor_sync(0xffffffffu, s, o);
        if (s > 256.f) lo = mid; else hi = mid;
    }

    // ---- 2 Newton updates from the left bracket ----
    float t = lo;
#pragma unroll
    for (int it = 0; it < 2; it++) {
        float s1 = 0.f, s2a = 0.f, s2b = 0.f;
#pragma unroll
        for (int j = 0; j < 32; j += 2) {
            float d0 = fmaxf(y[j]     - t, 0.f);
            float d1 = fmaxf(y[j + 1] - t, 0.f);
            s1 += d0 + d1;
            s2a = fmaf(d0, d0, s2a);
            s2b = fmaf(d1, d1, s2b);
        }
        float s2 = s2a + s2b;
#pragma unroll
        for (int o = 16; o > 0; o >>= 1) {
            s1 += __shfl_xor_sync(0xffffffffu, s1, o);
            s2 += __shfl_xor_sync(0xffffffffu, s2, o);
        }
        t += (s2 - 256.f) / (2.f * s1);
    }

    // ---- final sums at t (close to T*), closed form via transform ----
    float s1 = 0.f, s2 = 0.f, c = 0.f;
#pragma unroll
    for (int j = 0; j < 32; j++) {
        float d = y[j] - t;
        if (d > 0.f) { s1 += d; s2 = fmaf(d, d, s2); c += 1.f; }
    }
#pragma unroll
    for (int o = 16; o > 0; o >>= 1) {
        s1 += __shfl_xor_sync(0xffffffffu, s1, o);
        s2 += __shfl_xor_sync(0xffffffffu, s2, o);
        c  += __shfl_xor_sync(0xffffffffu, c,  o);
    }
    float SY   = s1 + c * t;
    float SY2  = s2 + 2.f * t * s1 + c * t * t;
    float disc = fmaxf(SY * SY - c * (SY2 - 256.f), 0.f);
    float T    = (SY - sqrtf(disc)) / c;

    // ---- compact support {y > T}: smem up to SUP_CAP, spill to Ovf ----
    int myc = 0;
#pragma unroll
    for (int j = 0; j < 32; j++)
        if (y[j] > T) myc++;

    int off = myc;
#pragma unroll
    for (int d = 1; d < 32; d <<= 1) {
        int n = __shfl_up_sync(0xffffffffu, off, d);
        if (lane >= d) off += n;
    }
    int total = __shfl_sync(0xffffffffu, off, 31);
    off -= myc;

    float2* ovf = Ovf + (size_t)grow * Sn;
    int wp = off;
#pragma unroll
    for (int j = 0; j < 32; j++) {
        if (y[j] > T) {
            float d = (y[j] - T) * 0.0625f;
            uint32_t pos = ((j >> 2) << 7) + (lane << 2) + (j & 3);
            float2 e = make_float2(d * d, __uint_as_float(pos));
            if (wp < SUP_CAP) cand[w][wp] = e; else ovf[wp] = e;
            wp++;
        }
    }
    __syncwarp();

    // ---- gather: ctx[row,:] = sum p_j * V[idx_j,:] (4-way unrolled) ----
    const float* V = qkv + (size_t)bb * Sn * D3 + 2 * Dn + hh * HD;
    const int nsm = total < SUP_CAP ? total : SUP_CAP;

    float ax = 0.f, ay = 0.f, bx = 0.f, by = 0.f;
    float cx = 0.f, cy = 0.f, dx = 0.f, dy = 0.f;
    int j = 0;
    for (; j + 4 <= nsm; j += 4) {
        float2 e0 = cand[w][j],     e1 = cand[w][j + 1];
        float2 e2 = cand[w][j + 2], e3 = cand[w][j + 3];
        const float2* v0 = (const float2*)(V + (size_t)__float_as_uint(e0.y) * D3);
        const float2* v1 = (const float2*)(V + (size_t)__float_as_uint(e1.y) * D3);
        const float2* v2 = (const float2*)(V + (size_t)__float_as_uint(e2.y) * D3);
        const float2* v3 = (const float2*)(V + (size_t)__float_as_uint(e3.y) * D3);
        float2 a = v0[lane], b = v1[lane], cc = v2[lane], dd = v3[lane];
        ax = fmaf(e0.x, a.x,  ax); ay = fmaf(e0.x, a.y,  ay);
        bx = fmaf(e1.x, b.x,  bx); by = fmaf(e1.x, b.y,  by);
        cx = fmaf(e2.x, cc.x, cx); cy = fmaf(e2.x, cc.y, cy);
        dx = fmaf(e3.x, dd.x, dx); dy = fmaf(e3.x, dd.y, dy);
    }
    for (; j < nsm; j++) {
        float2 e0 = cand[w][j];
        const float2* v0 = (const float2*)(V + (size_t)__float_as_uint(e0.y) * D3);
        float2 a = v0[lane];
        ax = fmaf(e0.x, a.x, ax); ay = fmaf(e0.x, a.y, ay);
    }
    for (; j < total; j++) {         // overflow tail (rare)
        float2 e0 = ovf[j];
        const float2* v0 = (const float2*)(V + (size_t)__float_as_uint(e0.y) * D3);
        float2 a = v0[lane];
        ax = fmaf(e0.x, a.x, ax); ay = fmaf(e0.x, a.y, ay);
    }

    float2* cr = (float2*)(ctx + (size_t)(bb * Sn + row) * Dn + hh * HD);
    cr[lane] = make_float2((ax + bx) + (cx + dx), (ay + by) + (cy + dy));
}

// ---------------------------------------------------------------------------
__device__ __forceinline__ float blkRedSum(float v, float* sm) {
#pragma unroll
    for (int o = 16; o > 0; o >>= 1) v += __shfl_xor_sync(0xffffffffu, v, o);
    int nw = blockDim.x >> 5;
    if ((threadIdx.x & 31) == 0) sm[threadIdx.x >> 5] = v;
    __syncthreads();
    if (threadIdx.x == 0) {
        float s = sm[0];
        for (int i = 1; i < nw; i++) s += sm[i];
        sm[0] = s;
    }
    __syncthreads();
    float r = sm[0];
    __syncthreads();
    return r;
}

// out = residual + LayerNorm(y) * g + b   (rows of 512, eps=1e-5, biased var)
__global__ __launch_bounds__(128)
void add_ln_kernel(const float* __restrict__ Y, const float* __restrict__ R,
                   const float* __restrict__ g, const float* __restrict__ b,
                   float* __restrict__ O)
{
    __shared__ float sm[4];
    size_t row = blockIdx.x;
    const float* y = Y + row * 512;
    int tid = threadIdx.x;

    float v[4];
#pragma unroll
    for (int j = 0; j < 4; j++) v[j] = y[tid + j * 128];
    float s = 0.f, ss = 0.f;
#pragma unroll
    for (int j = 0; j < 4; j++) { s += v[j]; ss = fmaf(v[j], v[j], ss); }
    s  = blkRedSum(s,  sm);
    ss = blkRedSum(ss, sm);
    float mean = s * (1.f / 512.f);
    float var  = ss * (1.f / 512.f) - mean * mean;
    float rstd = rsqrtf(var + 1e-5f);
#pragma unroll
    for (int j = 0; j < 4; j++) {
        int c = tid + j * 128;
        O[row * 512 + c] = R[row * 512 + c] + (v[j] - mean) * rstd * g[c] + b[c];
    }
}

// ---------------------------------------------------------------------------
extern "C" void kernel_launch(void* const* d_in, const int* in_sizes, int n_in,
                              void* d_out, int out_size)
{
    const float* x   = (const float*)d_in[0];
    const float* Wq  = (const float*)d_in[1];  const float* bq  = (const float*)d_in[2];
    const float* Wk  = (const float*)d_in[3];  const float* bk  = (const float*)d_in[4];
    const float* Wv  = (const float*)d_in[5];  const float* bv  = (const float*)d_in[6];
    const float* Wo  = (const float*)d_in[7];  const float* bo  = (const float*)d_in[8];
    const float* g1  = (const float*)d_in[9];  const float* be1 = (const float*)d_in[10];
    const float* W1  = (const float*)d_in[11]; const float* b1  = (const float*)d_in[12];
    const float* W2  = (const float*)d_in[13]; const float* b2  = (const float*)d_in[14];
    const float* g2  = (const float*)d_in[15]; const float* be2 = (const float*)d_in[16];
    float* out = (float*)d_out;

    float *qkv, *wcat, *bcat, *s, *ctx, *y, *x1, *h1, *y2;
    float2* ovf;
    cudaGetSymbolAddress((void**)&qkv,  gQKV);
    cudaGetSymbolAddress((void**)&wcat, gWcat);
    cudaGetSymbolAddress((void**)&bcat, gBcat);
    cudaGetSymbolAddress((void**)&s,    gS);
    cudaGetSymbolAddress((void**)&ovf,  gOvf);
    cudaGetSymbolAddress((void**)&ctx,  gCtx);
    cudaGetSymbolAddress((void**)&y,    gY);
    cudaGetSymbolAddress((void**)&x1,   gX1);
    cudaGetSymbolAddress((void**)&h1,   gH1);
    cudaGetSymbolAddress((void**)&y2,   gY2);

    const long long SD3 = (long long)Sn * D3;
    const long long SS  = (long long)Sn * Sn;

    // Opt in to >48KB dynamic smem for each instantiation
    constexpr size_t SM_BIG  = tg_smem_bytes(128, 128, 32, false);  // ~105 KB
    constexpr size_t SM_BIGT = tg_smem_bytes(128, 128, 32, true);   // ~108 KB
    cudaFuncSetAttribute((const void*)tgemm<128,128,32,64,32,EPI_BIAS,false>,
                         cudaFuncAttributeMaxDynamicSharedMemorySize, (int)SM_BIG);
    cudaFuncSetAttribute((const void*)tgemm<128,128,32,64,32,EPI_NONE,true>,
                         cudaFuncAttributeMaxDynamicSharedMemorySize, (int)SM_BIGT);
    cudaFuncSetAttribute((const void*)tgemm<128,128,32,64,32,EPI_MISH,false>,
                         cudaFuncAttributeMaxDynamicSharedMemorySize, (int)SM_BIG);

    // 0) pack QKV weights/biases
    concat_qkv<<<(Dn * Dn + 255) / 256, 256>>>(Wq, Wk, Wv, bq, bk, bv, wcat, bcat);

    // 1) QKV in one GEMM: [8192,512] @ [512,1536] + bias -> gQKV
    tgemm<128,128,32,64,32,EPI_BIAS,false>
        <<<dim3(D3 / 128, Mtok / 128, 1), 256, SM_BIG>>>(
        x, wcat, bcat, qkv, Mtok, D3, Dn, Dn, D3, D3, 0,0,0,0,0,0, 1);

    // 2) scores[b,h] = Q_h @ K_h^T (NT, K=64), batched over 64 (b,h)
    tgemm<128,128,32,64,32,EPI_NONE,true>
        <<<dim3(Sn / 128, Sn / 128, Bn * Hn), 256, SM_BIGT>>>(
        qkv, qkv + Dn, nullptr, s, Sn, Sn, HD, D3, D3, Sn,
        SD3, HD, SD3, HD, (long long)Hn * SS, SS, Hn);

    // 3+4) fused entmax tau solve + sparse P@V gather (warp per row)
    entmax_pv<<<NROWS / 8, 256>>>(s, qkv, ovf, ctx);

    // 5) y = ctx @ Wo + bo
    tgemm<128,128,32,64,32,EPI_BIAS,false>
        <<<dim3(Dn / 128, Mtok / 128, 1), 256, SM_BIG>>>(
        ctx, Wo, bo, y, Mtok, Dn, Dn, Dn, Dn, Dn, 0,0,0,0,0,0, 1);

    // 6) x1 = x + LN(y)
    add_ln_kernel<<<Mtok, 128>>>(y, x, g1, be1, x1);

    // 7) h1 = mish(x1 @ W1 + b1)  [8192,2048]
    tgemm<128,128,32,64,32,EPI_MISH,false>
        <<<dim3(Fn / 128, Mtok / 128, 1), 256, SM_BIG>>>(
        x1, W1, b1, h1, Mtok, Fn, Dn, Dn, Fn, Fn, 0,0,0,0,0,0, 1);

    // 8) y2 = h1 @ W2 + b2  [8192,512]
    tgemm<128,128,32,64,32,EPI_BIAS,false>
        <<<dim3(Dn / 128, Mtok / 128, 1), 256, SM_BIG>>>(
        h1, W2, b2, y2, Mtok, Dn, Fn, Fn, Dn, Dn, 0,0,0,0,0,0, 1);

    // 9) out = x1 + LN(y2)
    add_ln_kernel<<<Mtok, 128>>>(y2, x1, g2, be2, out);
}

// round 17
// speedup vs baseline: 1.0630x; 1.0009x over previous
#include <cuda_runtime.h>
#include <math.h>
#include <stdint.h>

// Problem constants
constexpr int Bn = 8, Sn = 1024, Dn = 512, Hn = 8, HD = 64, Fn = 2048;
constexpr int Mtok = Bn * Sn; // 8192
constexpr int D3 = 3 * Dn;    // 1536
constexpr int NROWS = Bn * Hn * Sn;   // 65536 attention rows

// Scratch (static device globals; no runtime allocation)
__device__ float  gQKV [(size_t)Mtok * D3];          // packed Q|K|V rows
__device__ float  gWcat[Dn * D3];
__device__ float  gBcat[D3];
__device__ float  gS   [(size_t)Bn * Hn * Sn * Sn];  // 256 MB raw scores
__device__ float2 gOvf [(size_t)NROWS * Sn];         // overflow spill (rarely touched)
__device__ float  gCtx [Mtok * Dn];
__device__ float  gY   [Mtok * Dn];
__device__ float  gX1  [Mtok * Dn];
__device__ float  gH1  [(size_t)Mtok * Fn];
__device__ float  gY2  [Mtok * Dn];

enum { EPI_NONE = 0, EPI_BIAS = 1, EPI_MISH = 2 };

// mish(x) = x*tanh(softplus(x)); with t=e^x, tanh(ln(1+t)) = (t^2+2t)/(t^2+2t+2)
__device__ __forceinline__ float mish_f(float v) {
    if (v > 20.f) return v;
    float t = __expf(v);
    float u = fmaf(t, t, 2.f * t);
    return __fdividef(v * u, u + 2.f);
}

__device__ __forceinline__ float to_tf32(float x) {
    float r;
    asm("cvt.rna.tf32.f32 %0, %1;" : "=f"(r) : "f"(x));
    return r;
}

__device__ __forceinline__ void cpa16(float* smem_dst, const float* gsrc) {
    uint32_t a = (uint32_t)__cvta_generic_to_shared(smem_dst);
    asm volatile("cp.async.cg.shared.global [%0], [%1], 16;" :: "r"(a), "l"(gsrc));
}
__device__ __forceinline__ void cp_commit() {
    asm volatile("cp.async.commit_group;");
}
template <int NN>
__device__ __forceinline__ void cp_wait() {
    asm volatile("cp.async.wait_group %0;" :: "n"(NN));
}

__device__ __forceinline__ void mma_tf32(float* acc, const uint32_t* a, const uint32_t* b) {
    asm volatile(
        "mma.sync.aligned.m16n8k8.row.col.f32.tf32.tf32.f32 "
        "{%0,%1,%2,%3}, {%4,%5,%6,%7}, {%8,%9}, {%0,%1,%2,%3};"
        : "+f"(acc[0]), "+f"(acc[1]), "+f"(acc[2]), "+f"(acc[3])
        : "r"(a[0]), "r"(a[1]), "r"(a[2]), "r"(a[3]), "r"(b[0]), "r"(b[1]));
}

// Host/device-consistent smem sizing (3-stage pipeline)
constexpr size_t tg_smem_bytes(int BM, int BN, int BK, bool BT) {
    int as = BM * (BK + 4);
    int bs = BT ? BN * (BK + 4) : BK * (BN + 8);
    return (size_t)(as + bs) * 3 * sizeof(float);
}

// ---------------------------------------------------------------------------
// tf32 tensor-core GEMM, 3-stage cp.async pipeline: C = A @ B (+bias)(+mish).
// BTRANS: B stored [N,K] (K contiguous) -> C = A @ B^T.
// ---------------------------------------------------------------------------
template <int BM, int BN, int BK, int WM, int WN, int EPI, bool BTRANS>
__global__ __launch_bounds__(256, 2)
void tgemm(const float* __restrict__ Ag, const float* __restrict__ Bg,
           const float* __restrict__ bias, float* __restrict__ Cg,
           int M, int N, int K, int lda, int ldb, int ldc,
           long long sA_b, long long sA_h,
           long long sB_b, long long sB_h,
           long long sC_b, long long sC_h, int Hdiv)
{
    constexpr int WARPS_N = BN / WN;
    constexpr int MI = WM / 16;
    constexpr int NI = WN / 8;
    constexpr int ASTR = BK + 4;
    constexpr int BNP  = BN + 8;
    constexpr int KQ   = BK / 4;             // 16B chunks per row
    constexpr int BS_ELEMS = BTRANS ? BN * ASTR : BK * BNP;

    extern __shared__ __align__(16) float dsm[];
    float* AsBase = dsm;                          // 3 * BM * ASTR
    float* BsBase = dsm + 3 * BM * ASTR;          // 3 * BS_ELEMS

    int z  = blockIdx.z;
    int bb = z / Hdiv, hh = z - bb * Hdiv;
    const float* A = Ag + (size_t)bb * sA_b + (size_t)hh * sA_h;
    const float* B = Bg + (size_t)bb * sB_b + (size_t)hh * sB_h;
    float*       C = Cg + (size_t)bb * sC_b + (size_t)hh * sC_h;

    const int tid  = threadIdx.x;
    const int lane = tid & 31;
    const int w    = tid >> 5;
    const int gid  = lane >> 2;   // 0..7
    const int tig  = lane & 3;    // 0..3
    const int wm0  = (w / WARPS_N) * WM;
    const int wn0  = (w % WARPS_N) * WN;
    const int m0   = blockIdx.y * BM;
    const int n0   = blockIdx.x * BN;

    float acc[MI][NI][4];
#pragma unroll
    for (int i = 0; i < MI; i++)
#pragma unroll
        for (int j = 0; j < NI; j++)
#pragma unroll
            for (int c = 0; c < 4; c++) acc[i][j][c] = 0.f;

    const int nTiles = K / BK;

    auto load_tile = [&](int kt, int buf) {
        float* As = AsBase + buf * (BM * ASTR);
        float* Bs = BsBase + buf * BS_ELEMS;
#pragma unroll
        for (int i = tid; i < BM * KQ; i += 256) {
            int m = i / KQ, kc = (i % KQ) * 4;
            cpa16(&As[m * ASTR + kc], A + (size_t)(m0 + m) * lda + kt * BK + kc);
        }
        if (BTRANS) {
#pragma unroll
            for (int i = tid; i < BN * KQ; i += 256) {
                int n = i / KQ, kc = (i % KQ) * 4;
                cpa16(&Bs[n * ASTR + kc], B + (size_t)(n0 + n) * ldb + kt * BK + kc);
            }
        } else {
#pragma unroll
            for (int i = tid; i < BK * BN / 4; i += 256) {
                int kr = i / (BN / 4), nq = (i % (BN / 4)) * 4;
                cpa16(&Bs[kr * BNP + nq], B + (size_t)(kt * BK + kr) * ldb + n0 + nq);
            }
        }
        cp_commit();
    };

    load_tile(0, 0);
    load_tile(1, 1);

    for (int kt = 0; kt < nTiles; kt++) {
        if (kt + 1 >= nTiles) cp_wait<0>(); else cp_wait<1>();
        __syncthreads();
        if (kt + 2 < nTiles) load_tile(kt + 2, (kt + 2) % 3);

        int buf = kt % 3;
        const float* As = AsBase + buf * (BM * ASTR);
        const float* Bs = BsBase + buf * BS_ELEMS;

#pragma unroll
        for (int ks = 0; ks < BK; ks += 8) {
            uint32_t af[MI][4], bf[NI][2];
#pragma unroll
            for (int mi = 0; mi < MI; mi++) {
                const float* ap = As + (wm0 + mi * 16 + gid) * ASTR + ks + tig;
                af[mi][0] = __float_as_uint(to_tf32(ap[0]));
                af[mi][1] = __float_as_uint(to_tf32(ap[8 * ASTR]));
                af[mi][2] = __float_as_uint(to_tf32(ap[4]));
                af[mi][3] = __float_as_uint(to_tf32(ap[8 * ASTR + 4]));
            }
#pragma unroll
            for (int ni = 0; ni < NI; ni++) {
                if (BTRANS) {
                    const float* bp = Bs + (wn0 + ni * 8 + gid) * ASTR + ks + tig;
                    bf[ni][0] = __float_as_uint(to_tf32(bp[0]));
                    bf[ni][1] = __float_as_uint(to_tf32(bp[4]));
                } else {
                    const float* bp = Bs + (ks + tig) * BNP + wn0 + ni * 8 + gid;
                    bf[ni][0] = __float_as_uint(to_tf32(bp[0]));
                    bf[ni][1] = __float_as_uint(to_tf32(bp[4 * BNP]));
                }
            }
#pragma unroll
            for (int mi = 0; mi < MI; mi++)
#pragma unroll
                for (int ni = 0; ni < NI; ni++)
                    mma_tf32(acc[mi][ni], af[mi], bf[ni]);
        }
    }

    // --- Epilogue ---
#pragma unroll
    for (int mi = 0; mi < MI; mi++) {
#pragma unroll
        for (int ni = 0; ni < NI; ni++) {
            int row = m0 + wm0 + mi * 16 + gid;
            int col = n0 + wn0 + ni * 8 + tig * 2;
            float b0 = 0.f, b1 = 0.f;
            if (EPI >= 1) { b0 = bias[col]; b1 = bias[col + 1]; }
            float v0 = acc[mi][ni][0] + b0, v1 = acc[mi][ni][1] + b1;
            float v2 = acc[mi][ni][2] + b0, v3 = acc[mi][ni][3] + b1;
            if (EPI == 2) { v0 = mish_f(v0); v1 = mish_f(v1); v2 = mish_f(v2); v3 = mish_f(v3); }
            *(float2*)(C + (size_t)row * ldc + col)       = make_float2(v0, v1);
            *(float2*)(C + (size_t)(row + 8) * ldc + col) = make_float2(v2, v3);
        }
    }
}

// ---------------------------------------------------------------------------
// Pack Wq|Wk|Wv -> gWcat [512][1536], biases -> gBcat [1536]
// ---------------------------------------------------------------------------
__global__ __launch_bounds__(256)
void concat_qkv(const float* __restrict__ Wq, const float* __restrict__ Wk,
                const float* __restrict__ Wv,
                const float* __restrict__ bq, const float* __restrict__ bk,
                const float* __restrict__ bv,
                float* __restrict__ Wcat, float* __restrict__ bcat)
{
    int i = blockIdx.x * 256 + threadIdx.x;
    if (i < Dn * Dn) {
        int k = i >> 9, n = i & 511;
        Wcat[k * D3 + n]          = Wq[i];
        Wcat[k * D3 + Dn + n]     = Wk[i];
        Wcat[k * D3 + 2 * Dn + n] = Wv[i];
    }
    if (i < Dn) {
        bcat[i]          = bq[i];
        bcat[Dn + i]     = bk[i];
        bcat[2 * Dn + i] = bv[i];
    }
}

// ---------------------------------------------------------------------------
// Fused entmax-1.5 + sparse attn@V, warp per attention row.
// Score row staged into SMEM via cp.async (no y[32] register array):
// registers drop to ~35 so occupancy is smem-limited at 5 CTAs/SM (62.5%).
// All solver passes walk the row as conflict-free float4 LDS
// (pos = 4*(wq*32+lane)+c -- identical element ordering to the register
// version, so numerics are bit-identical).
// Phase A: raw-domain tau solve (max, 3 bisect, 2 Newton, final sums +
//          closed-form via SY = s1 + c*t, SY2 = s2 + 2t*s1 + c*t^2).
// Phase B: compact support {y > T} into smem (cap 128; global spill).
// Phase C: gather ctx[row,:] = sum p_j * V[idx_j,:] (fp32, 4-way unroll).
// ---------------------------------------------------------------------------
constexpr int SUP_CAP = 128;

__global__ __launch_bounds__(256, 5)
void entmax_pv(const float* __restrict__ S, const float* __restrict__ qkv,
               float2* __restrict__ Ovf, float* __restrict__ ctx)
{
    __shared__ __align__(16) float Ys[8][1024];   // 32 KB
    __shared__ float2 cand[8][SUP_CAP];           // 8 KB

    const int w    = threadIdx.x >> 5;
    const int lane = threadIdx.x & 31;
    const int grow = blockIdx.x * 8 + w;         // global row
    const int z    = grow >> 10;                 // (b,h)
    const int row  = grow & 1023;
    const int bb   = z >> 3, hh = z & 7;

    // ---- stage row into smem (coalesced cp.async) ----
    {
        const float* src = S + (size_t)grow * 1024;
#pragma unroll
        for (int wq = 0; wq < 8; wq++) {
            int i = wq * 32 + lane;
            cpa16(&Ys[w][i * 4], src + i * 4);
        }
        cp_commit();
        cp_wait<0>();
    }
    __syncthreads();

    const float4* ys = (const float4*)Ys[w];

    // ---- max ----
    float m = -3.4e38f;
#pragma unroll
    for (int wq = 0; wq < 8; wq++) {
        float4 v = ys[wq * 32 + lane];
        m = fmaxf(m, fmaxf(fmaxf(v.x, v.y), fmaxf(v.z, v.w)));
    }
#pragma unroll
    for (int o = 16; o > 0; o >>= 1) m = fmaxf(m, __shfl_xor_sync(0xffffffffu, m, o));

    // ---- 3 bisections: T* in [m-16, m], f(lo) >= 256 invariant ----
    float lo = m - 16.f, hi = m;
#pragma unroll
    for (int it = 0; it < 3; it++) {
        float mid = 0.5f * (lo + hi);
        float sa = 0.f, sb = 0.f;
#pragma unroll
        for (int wq = 0; wq < 8; wq++) {
            float4 v = ys[wq * 32 + lane];
            float d0 = fmaxf(v.x - mid, 0.f), d1 = fmaxf(v.y - mid, 0.f);
            float d2 = fmaxf(v.z - mid, 0.f), d3 = fmaxf(v.w - mid, 0.f);
            sa = fmaf(d0, d0, sa); sb = fmaf(d1, d1, sb);
            sa = fmaf(d2, d2, sa); sb = fmaf(d3, d3, sb);
        }
        float s = sa + sb;
#pragma unroll
        for (int o = 16; o > 0; o >>= 1) s += __shfl_xor_sync(0xffffffffu, s, o);
        if (s > 256.f) lo = mid; else hi = mid;
    }

    // ---- 2 Newton updates from the left bracket ----
    float t = lo;
#pragma unroll
    for (int it = 0; it < 2; it++) {
        float s1 = 0.f, s2a = 0.f, s2b = 0.f;
#pragma unroll
        for (int wq = 0; wq < 8; wq++) {
            float4 v = ys[wq * 32 + lane];
            float d0 = fmaxf(v.x - t, 0.f), d1 = fmaxf(v.y - t, 0.f);
            float d2 = fmaxf(v.z - t, 0.f), d3 = fmaxf(v.w - t, 0.f);
            s1 += (d0 + d1) + (d2 + d3);
            s2a = fmaf(d0, d0, s2a); s2b = fmaf(d1, d1, s2b);
            s2a = fmaf(d2, d2, s2a); s2b = fmaf(d3, d3, s2b);
        }
        float s2 = s2a + s2b;
#pragma unroll
        for (int o = 16; o > 0; o >>= 1) {
            s1 += __shfl_xor_sync(0xffffffffu, s1, o);
            s2 += __shfl_xor_sync(0xffffffffu, s2, o);
        }
        t += (s2 - 256.f) / (2.f * s1);
    }

    // ---- final sums at t (close to T*), closed form via transform ----
    float s1 = 0.f, s2 = 0.f, c = 0.f;
#pragma unroll
    for (int wq = 0; wq < 8; wq++) {
        float4 v = ys[wq * 32 + lane];
        float dd[4] = {v.x - t, v.y - t, v.z - t, v.w - t};
#pragma unroll
        for (int k = 0; k < 4; k++) {
            if (dd[k] > 0.f) { s1 += dd[k]; s2 = fmaf(dd[k], dd[k], s2); c += 1.f; }
        }
    }
#pragma unroll
    for (int o = 16; o > 0; o >>= 1) {
        s1 += __shfl_xor_sync(0xffffffffu, s1, o);
        s2 += __shfl_xor_sync(0xffffffffu, s2, o);
        c  += __shfl_xor_sync(0xffffffffu, c,  o);
    }
    float SY   = s1 + c * t;
    float SY2  = s2 + 2.f * t * s1 + c * t * t;
    float disc = fmaxf(SY * SY - c * (SY2 - 256.f), 0.f);
    float T    = (SY - sqrtf(disc)) / c;

    // ---- count support {y > T} ----
    int myc = 0;
#pragma unroll
    for (int wq = 0; wq < 8; wq++) {
        float4 v = ys[wq * 32 + lane];
        if (v.x > T) myc++;
        if (v.y > T) myc++;
        if (v.z > T) myc++;
        if (v.w > T) myc++;
    }
    int off = myc;
#pragma unroll
    for (int d = 1; d < 32; d <<= 1) {
        int n = __shfl_up_sync(0xffffffffu, off, d);
        if (lane >= d) off += n;
    }
    int total = __shfl_sync(0xffffffffu, off, 31);
    off -= myc;

    // ---- write support (p, idx): smem up to SUP_CAP, spill to Ovf ----
    float2* ovf = Ovf + (size_t)grow * Sn;
    int wp = off;
#pragma unroll
    for (int wq = 0; wq < 8; wq++) {
        int i = wq * 32 + lane;
        float4 v = ys[i];
        float vv[4] = {v.x, v.y, v.z, v.w};
#pragma unroll
        for (int k = 0; k < 4; k++) {
            if (vv[k] > T) {
                float d = (vv[k] - T) * 0.0625f;
                uint32_t pos = 4 * i + k;
                float2 e = make_float2(d * d, __uint_as_float(pos));
                if (wp < SUP_CAP) cand[w][wp] = e; else ovf[wp] = e;
                wp++;
            }
        }
    }
    __syncwarp();

    // ---- gather: ctx[row,:] = sum p_j * V[idx_j,:] (4-way unrolled) ----
    const float* V = qkv + (size_t)bb * Sn * D3 + 2 * Dn + hh * HD;
    const int nsm = total < SUP_CAP ? total : SUP_CAP;

    float ax = 0.f, ay = 0.f, bx = 0.f, by = 0.f;
    float cx = 0.f, cy = 0.f, dx = 0.f, dy = 0.f;
    int j = 0;
    for (; j + 4 <= nsm; j += 4) {
        float2 e0 = cand[w][j],     e1 = cand[w][j + 1];
        float2 e2 = cand[w][j + 2], e3 = cand[w][j + 3];
        const float2* v0 = (const float2*)(V + (size_t)__float_as_uint(e0.y) * D3);
        const float2* v1 = (const float2*)(V + (size_t)__float_as_uint(e1.y) * D3);
        const float2* v2 = (const float2*)(V + (size_t)__float_as_uint(e2.y) * D3);
        const float2* v3 = (const float2*)(V + (size_t)__float_as_uint(e3.y) * D3);
        float2 a = v0[lane], b = v1[lane], cc = v2[lane], dd = v3[lane];
        ax = fmaf(e0.x, a.x,  ax); ay = fmaf(e0.x, a.y,  ay);
        bx = fmaf(e1.x, b.x,  bx); by = fmaf(e1.x, b.y,  by);
        cx = fmaf(e2.x, cc.x, cx); cy = fmaf(e2.x, cc.y, cy);
        dx = fmaf(e3.x, dd.x, dx); dy = fmaf(e3.x, dd.y, dy);
    }
    for (; j < nsm; j++) {
        float2 e0 = cand[w][j];
        const float2* v0 = (const float2*)(V + (size_t)__float_as_uint(e0.y) * D3);
        float2 a = v0[lane];
        ax = fmaf(e0.x, a.x, ax); ay = fmaf(e0.x, a.y, ay);
    }
    for (; j < total; j++) {         // overflow tail (rare)
        float2 e0 = ovf[j];
        const float2* v0 = (const float2*)(V + (size_t)__float_as_uint(e0.y) * D3);
        float2 a = v0[lane];
        ax = fmaf(e0.x, a.x, ax); ay = fmaf(e0.x, a.y, ay);
    }

    float2* cr = (float2*)(ctx + (size_t)(bb * Sn + row) * Dn + hh * HD);
    cr[lane] = make_float2((ax + bx) + (cx + dx), (ay + by) + (cy + dy));
}

// ---------------------------------------------------------------------------
__device__ __forceinline__ float blkRedSum(float v, float* sm) {
#pragma unroll
    for (int o = 16; o > 0; o >>= 1) v += __shfl_xor_sync(0xffffffffu, v, o);
    int nw = blockDim.x >> 5;
    if ((threadIdx.x & 31) == 0) sm[threadIdx.x >> 5] = v;
    __syncthreads();
    if (threadIdx.x == 0) {
        float s = sm[0];
        for (int i = 1; i < nw; i++) s += sm[i];
        sm[0] = s;
    }
    __syncthreads();
    float r = sm[0];
    __syncthreads();
    return r;
}

// out = residual + LayerNorm(y) * g + b   (rows of 512, eps=1e-5, biased var)
__global__ __launch_bounds__(128)
void add_ln_kernel(const float* __restrict__ Y, const float* __restrict__ R,
                   const float* __restrict__ g, const float* __restrict__ b,
                   float* __restrict__ O)
{
    __shared__ float sm[4];
    size_t row = blockIdx.x;
    const float* y = Y + row * 512;
    int tid = threadIdx.x;

    float v[4];
#pragma unroll
    for (int j = 0; j < 4; j++) v[j] = y[tid + j * 128];
    float s = 0.f, ss = 0.f;
#pragma unroll
    for (int j = 0; j < 4; j++) { s += v[j]; ss = fmaf(v[j], v[j], ss); }
    s  = blkRedSum(s,  sm);
    ss = blkRedSum(ss, sm);
    float mean = s * (1.f / 512.f);
    float var  = ss * (1.f / 512.f) - mean * mean;
    float rstd = rsqrtf(var + 1e-5f);
#pragma unroll
    for (int j = 0; j < 4; j++) {
        int c = tid + j * 128;
        O[row * 512 + c] = R[row * 512 + c] + (v[j] - mean) * rstd * g[c] + b[c];
    }
}

// ---------------------------------------------------------------------------
extern "C" void kernel_launch(void* const* d_in, const int* in_sizes, int n_in,
                              void* d_out, int out_size)
{
    const float* x   = (const float*)d_in[0];
    const float* Wq  = (const float*)d_in[1];  const float* bq  = (const float*)d_in[2];
    const float* Wk  = (const float*)d_in[3];  const float* bk  = (const float*)d_in[4];
    const float* Wv  = (const float*)d_in[5];  const float* bv  = (const float*)d_in[6];
    const float* Wo  = (const float*)d_in[7];  const float* bo  = (const float*)d_in[8];
    const float* g1  = (const float*)d_in[9];  const float* be1 = (const float*)d_in[10];
    const float* W1  = (const float*)d_in[11]; const float* b1  = (const float*)d_in[12];
    const float* W2  = (const float*)d_in[13]; const float* b2  = (const float*)d_in[14];
    const float* g2  = (const float*)d_in[15]; const float* be2 = (const float*)d_in[16];
    float* out = (float*)d_out;

    float *qkv, *wcat, *bcat, *s, *ctx, *y, *x1, *h1, *y2;
    float2* ovf;
    cudaGetSymbolAddress((void**)&qkv,  gQKV);
    cudaGetSymbolAddress((void**)&wcat, gWcat);
    cudaGetSymbolAddress((void**)&bcat, gBcat);
    cudaGetSymbolAddress((void**)&s,    gS);
    cudaGetSymbolAddress((void**)&ovf,  gOvf);
    cudaGetSymbolAddress((void**)&ctx,  gCtx);
    cudaGetSymbolAddress((void**)&y,    gY);
    cudaGetSymbolAddress((void**)&x1,   gX1);
    cudaGetSymbolAddress((void**)&h1,   gH1);
    cudaGetSymbolAddress((void**)&y2,   gY2);

    const long long SD3 = (long long)Sn * D3;
    const long long SS  = (long long)Sn * Sn;

    // Opt in to >48KB dynamic smem for each instantiation
    constexpr size_t SM_BIG  = tg_smem_bytes(128, 128, 32, false);  // ~105 KB
    constexpr size_t SM_BIGT = tg_smem_bytes(128, 128, 32, true);   // ~108 KB
    cudaFuncSetAttribute((const void*)tgemm<128,128,32,64,32,EPI_BIAS,false>,
                         cudaFuncAttributeMaxDynamicSharedMemorySize, (int)SM_BIG);
    cudaFuncSetAttribute((const void*)tgemm<128,128,32,64,32,EPI_NONE,true>,
                         cudaFuncAttributeMaxDynamicSharedMemorySize, (int)SM_BIGT);
    cudaFuncSetAttribute((const void*)tgemm<128,128,32,64,32,EPI_MISH,false>,
                         cudaFuncAttributeMaxDynamicSharedMemorySize, (int)SM_BIG);

    // 0) pack QKV weights/biases
    concat_qkv<<<(Dn * Dn + 255) / 256, 256>>>(Wq, Wk, Wv, bq, bk, bv, wcat, bcat);

    // 1) QKV in one GEMM: [8192,512] @ [512,1536] + bias -> gQKV
    tgemm<128,128,32,64,32,EPI_BIAS,false>
        <<<dim3(D3 / 128, Mtok / 128, 1), 256, SM_BIG>>>(
        x, wcat, bcat, qkv, Mtok, D3, Dn, Dn, D3, D3, 0,0,0,0,0,0, 1);

    // 2) scores[b,h] = Q_h @ K_h^T (NT, K=64), batched over 64 (b,h)
    tgemm<128,128,32,64,32,EPI_NONE,true>
        <<<dim3(Sn / 128, Sn / 128, Bn * Hn), 256, SM_BIGT>>>(
        qkv, qkv + Dn, nullptr, s, Sn, Sn, HD, D3, D3, Sn,
        SD3, HD, SD3, HD, (long long)Hn * SS, SS, Hn);

    // 3+4) fused entmax tau solve + sparse P@V gather (warp per row, smem row)
    entmax_pv<<<NROWS / 8, 256>>>(s, qkv, ovf, ctx);

    // 5) y = ctx @ Wo + bo
    tgemm<128,128,32,64,32,EPI_BIAS,false>
        <<<dim3(Dn / 128, Mtok / 128, 1), 256, SM_BIG>>>(
        ctx, Wo, bo, y, Mtok, Dn, Dn, Dn, Dn, Dn, 0,0,0,0,0,0, 1);

    // 6) x1 = x + LN(y)
    add_ln_kernel<<<Mtok, 128>>>(y, x, g1, be1, x1);

    // 7) h1 = mish(x1 @ W1 + b1)  [8192,2048]
    tgemm<128,128,32,64,32,EPI_MISH,false>
        <<<dim3(Fn / 128, Mtok / 128, 1), 256, SM_BIG>>>(
        x1, W1, b1, h1, Mtok, Fn, Dn, Dn, Fn, Fn, 0,0,0,0,0,0, 1);

    // 8) y2 = h1 @ W2 + b2  [8192,512]
    tgemm<128,128,32,64,32,EPI_BIAS,false>
        <<<dim3(Dn / 128, Mtok / 128, 1), 256, SM_BIG>>>(
        h1, W2, b2, y2, Mtok, Dn, Fn, Fn, Dn, Dn, 0,0,0,0,0,0, 1);

    // 9) out = x1 + LN(y2)
    add_ln_kernel<<<Mtok, 128>>>(y2, x1, g2, be2, out);
}